// round 11
// baseline (speedup 1.0000x reference)
#include <cuda_runtime.h>
#include <cuda_bf16.h>
#include <math.h>
#include <stdint.h>

#define BB 2
#define NNODES 4096
#define DIMF 128
#define KNN 32
#define HID 530
#define EPAD 544                    // padded hidden (17*32)
#define NODES (BB*NNODES)           // 8192
#define NODE_OUT_ELEMS (NODES*DIMF)

typedef unsigned long long ull;

// ---------------- scratch (static device arrays; no allocation) -------------
__device__ float g_A[NODES * EPAD];    // feats@We1[0:128]+be1 (pad cols zero)
__device__ float g_B[NODES * EPAD];    // feats@We1[128:256]   (pad cols zero)
__device__ float g_XC[NODES * 144];    // [feats | m_i]
__device__ float g_H1[NODES * 256];    // node hidden
__device__ int   g_knn[NODES * KNN];

// ---------------- f32x2 helpers ---------------------------------------------
__device__ __forceinline__ ull pack2(float lo, float hi) {
    ull u; asm("mov.b64 %0, {%1, %2};" : "=l"(u) : "f"(lo), "f"(hi)); return u;
}
__device__ __forceinline__ float2 unpack2(ull u) {
    float2 v; asm("mov.b64 {%0, %1}, %2;" : "=f"(v.x), "=f"(v.y) : "l"(u)); return v;
}
__device__ __forceinline__ void ffma2(ull& d, ull a, ull b) {
    asm("fma.rn.f32x2 %0, %1, %2, %0;" : "+l"(d) : "l"(a), "l"(b));
}
__device__ __forceinline__ ull fadd2(ull a, ull b) {
    ull d; asm("add.rn.f32x2 %0, %1, %2;" : "=l"(d) : "l"(a), "l"(b)); return d;
}

__device__ __forceinline__ float silu_f(float x) {
    float e = __expf(-x);
    return __fdividef(x, 1.0f + e);
}

__device__ __forceinline__ float dist2_f(float dx, float dy, float dz) {
    return __fadd_rn(__fadd_rn(__fmul_rn(dx, dx), __fmul_rn(dy, dy)), __fmul_rn(dz, dz));
}

// ---------------------------------------------------------------------------
// KNN: one warp per (b,i). Unsorted top-32 set via warp REDUX threshold.
// ---------------------------------------------------------------------------
__global__ __launch_bounds__(256) void knn_kernel(const float* __restrict__ coors) {
    const unsigned FULL = 0xffffffffu;
    int w    = blockIdx.x * 8 + (threadIdx.x >> 5);
    int lane = threadIdx.x & 31;
    int b = w >> 12;
    int i = w & (NNODES - 1);
    const float* cb = coors + (size_t)b * NNODES * 3;
    float qx = cb[3 * i + 0], qy = cb[3 * i + 1], qz = cb[3 * i + 2];

    float dx = qx - cb[3 * lane + 0];
    float dy = qy - cb[3 * lane + 1];
    float dz = qz - cb[3 * lane + 2];
    unsigned bu = __float_as_uint(dist2_f(dx, dy, dz));
    int bj = lane;
    unsigned curmax = __reduce_max_sync(FULL, bu);

    for (int j0 = 32; j0 < NNODES; j0 += 32) {
        int j = j0 + lane;
        float ex = qx - cb[3 * j + 0];
        float ey = qy - cb[3 * j + 1];
        float ez = qz - cb[3 * j + 2];
        unsigned du = __float_as_uint(dist2_f(ex, ey, ez));
        unsigned mask = __ballot_sync(FULL, du < curmax);
        while (mask) {
            int src = __ffs(mask) - 1;
            mask &= mask - 1;
            unsigned dc = __shfl_sync(FULL, du, src);
            if (dc < curmax) {
                unsigned mm = __ballot_sync(FULL, bu == curmax);
                int ml = __ffs(mm) - 1;
                if (lane == ml) { bu = dc; bj = j0 + src; }
                curmax = __reduce_max_sync(FULL, bu);
            }
        }
    }
    g_knn[(size_t)w * KNN + lane] = bj;
}

// ---------------------------------------------------------------------------
// Tiled fp32 GEMM (FFMA2): C[.. x Npad] = act(X @ W + b) (+resid); pads -> 0
// ---------------------------------------------------------------------------
__global__ __launch_bounds__(256) void gemm_kernel(
    const float* __restrict__ X, int ldx,
    const float* __restrict__ W, int ldw,
    const float* __restrict__ bias,
    const float* __restrict__ resid, int ldr,
    float* __restrict__ C, int ldc,
    int Nw, int Npad, int K, int act)
{
    __shared__ float Xs[16][68];
    __shared__ float Ws[16][68];
    int tid = threadIdx.x;
    int tx = tid & 15, ty = tid >> 4;
    int m0 = blockIdx.y * 64, n0 = blockIdx.x * 64;

    int lm  = tid >> 2;
    int lk  = (tid & 3) * 4;
    int wn  = tid & 63;
    int wkb = (tid >> 6) * 4;

    ull acc2[4][2];
#pragma unroll
    for (int a = 0; a < 4; a++) { acc2[a][0] = 0ull; acc2[a][1] = 0ull; }

    for (int kt = 0; kt < K; kt += 16) {
        float4 xv = *reinterpret_cast<const float4*>(X + (size_t)(m0 + lm) * ldx + kt + lk);
        Xs[lk + 0][lm] = xv.x;
        Xs[lk + 1][lm] = xv.y;
        Xs[lk + 2][lm] = xv.z;
        Xs[lk + 3][lm] = xv.w;
#pragma unroll
        for (int q = 0; q < 4; q++) {
            int k = wkb + q;
            float v = (n0 + wn < Nw) ? W[(size_t)(kt + k) * ldw + n0 + wn] : 0.f;
            Ws[k][wn] = v;
        }
        __syncthreads();
#pragma unroll
        for (int k = 0; k < 16; k++) {
            float4 a4 = *reinterpret_cast<const float4*>(&Xs[k][ty * 4]);
            float4 b4 = *reinterpret_cast<const float4*>(&Ws[k][tx * 4]);
            ull b01 = pack2(b4.x, b4.y);
            ull b23 = pack2(b4.z, b4.w);
            float av[4] = {a4.x, a4.y, a4.z, a4.w};
#pragma unroll
            for (int mi = 0; mi < 4; mi++) {
                ull aa = pack2(av[mi], av[mi]);
                ffma2(acc2[mi][0], aa, b01);
                ffma2(acc2[mi][1], aa, b23);
            }
        }
        __syncthreads();
    }

#pragma unroll
    for (int mi = 0; mi < 4; mi++) {
        int m = m0 + ty * 4 + mi;
        float2 lo = unpack2(acc2[mi][0]);
        float2 hi = unpack2(acc2[mi][1]);
        float accv[4] = {lo.x, lo.y, hi.x, hi.y};
#pragma unroll
        for (int ni = 0; ni < 4; ni++) {
            int n = n0 + tx * 4 + ni;
            if (n < Npad) {
                float v = accv[ni];
                if (n < Nw) {
                    if (bias) v += bias[n];
                    if (act) v = silu_f(v);
                    if (resid) v += resid[(size_t)m * ldr + n];
                } else {
                    v = 0.f;
                }
                C[(size_t)m * ldc + n] = v;
            }
        }
    }
}

// ---------------------------------------------------------------------------
__global__ __launch_bounds__(256) void copy_feats_kernel(const float* __restrict__ feats) {
    int idx = blockIdx.x * 256 + threadIdx.x;  // over NODES*128
    int n = idx >> 7, c = idx & 127;
    g_XC[(size_t)n * 144 + c] = feats[idx];
}

// ---------------------------------------------------------------------------
// Edge kernel v3: 256 threads (8 warps), 4 nodes/block, 2 blocks/SM.
// Warp w owns edges 4w..4w+3 (ALL channels); lanes stride channels.
// Lane-strided weight loads (every byte useful) amortized over 4 edges.
// Fourier terms: 4 f32x2 pairs + scalar d per edge in registers.
// 32-value f32x2 reduce-scatter: lane l ends with edge e0+(l>>3), k=2(l&7).
// ---------------------------------------------------------------------------
// byte offsets in dynamic smem:
#define OFF_WE2  0                                // ulonglong2[EPAD*4] = 34816
#define OFF_W9A  34816                            // ulonglong2[EPAD*2] = 17408
#define OFF_W9B  52224                            // ull[EPAD]          = 4352
#define OFF_AS   56576                            // float[EPAD]        = 2176
#define OFF_F2   58752                            // ull[32*6]          = 1536
#define OFF_FLT  60288
#define FI_WC1 0
#define FI_BC1 1024
#define FI_WC2 1088
#define FI_BE2 1152
#define FI_RC  1168
#define FI_MS  1296
#define FI_CW  1808
#define FI_EBO 1840
#define FI_TOT 1872
#define EK_SMEM_BYTES (OFF_FLT + FI_TOT*4)        // 67776

__global__ __launch_bounds__(256, 2) void edge_kernel(
    const float* __restrict__ coors,
    const float* __restrict__ We1,
    const float* __restrict__ We2,
    const float* __restrict__ be2,
    const float* __restrict__ Wc1,
    const float* __restrict__ bc1,
    const float* __restrict__ Wc2,
    const float* __restrict__ bc2,
    float* __restrict__ coors_out)
{
    extern __shared__ char smc[];
    ulonglong2* We2q = (ulonglong2*)(smc + OFF_WE2);   // [c*4+p] -> outputs 4p..4p+3
    ulonglong2* W9A  = (ulonglong2*)(smc + OFF_W9A);   // [c*2+t] -> fourier terms 4t..4t+3
    ull* W9B = (ull*)(smc + OFF_W9B);                  // [c] -> (term8, 0)
    float* As  = (float*)(smc + OFF_AS);
    ull* F2u = (ull*)(smc + OFF_F2);                   // [32][6] per-edge fourier pairs
    float* smf  = (float*)(smc + OFF_FLT);
    float* Wc1s = smf + FI_WC1;
    float* bc1s = smf + FI_BC1;
    float* Wc2s = smf + FI_WC2;
    float* be2s = smf + FI_BE2;
    float* rc_s = smf + FI_RC;                         // [32][4]
    float* ms   = smf + FI_MS;                         // [32][16]
    float* cw_s = smf + FI_CW;                         // [32]
    uint32_t* ebo_s = (uint32_t*)(smf + FI_EBO);       // [32]

    int tid = threadIdx.x;
    int w = tid >> 5, lane = tid & 31;
    const unsigned FULL = 0xffffffffu;
    float bc2v = bc2[0];

    // ---- weight preamble (once per block) ----
    for (int idx = tid; idx < 4 * EPAD; idx += 256) {
        int c = idx >> 2, p = idx & 3;
        ulonglong2 v; v.x = 0ull; v.y = 0ull;
        if (c < HID) {
            v.x = pack2(We2[c * 16 + 4 * p + 0], We2[c * 16 + 4 * p + 1]);
            v.y = pack2(We2[c * 16 + 4 * p + 2], We2[c * 16 + 4 * p + 3]);
        }
        We2q[idx] = v;
    }
    for (int idx = tid; idx < 2 * EPAD; idx += 256) {
        int c = idx >> 1, t = idx & 1;
        ulonglong2 v; v.x = 0ull; v.y = 0ull;
        if (c < HID) {
            v.x = pack2(We1[(size_t)(256 + 4 * t + 0) * HID + c], We1[(size_t)(256 + 4 * t + 1) * HID + c]);
            v.y = pack2(We1[(size_t)(256 + 4 * t + 2) * HID + c], We1[(size_t)(256 + 4 * t + 3) * HID + c]);
        }
        W9A[idx] = v;
    }
    for (int c = tid; c < EPAD; c += 256) {
        ull v = 0ull;
        if (c < HID) v = pack2(We1[(size_t)264 * HID + c], 0.f);
        W9B[c] = v;
    }
    for (int idx = tid; idx < 16 * 64; idx += 256) Wc1s[idx] = Wc1[idx];
    if (tid < 64) { bc1s[tid] = bc1[tid]; Wc2s[tid] = Wc2[tid]; }
    if (tid >= 64 && tid < 80) be2s[tid - 64] = be2[tid - 64];
    __syncthreads();

#pragma unroll 1
    for (int nn = 0; nn < 4; nn++) {
        int node = blockIdx.x * 4 + nn;
        int b = node >> 12, i = node & (NNODES - 1);
        const float* cb = coors + (size_t)b * NNODES * 3;
        const float* Ap = g_A + (size_t)node * EPAD;

        // ---- per-node setup: A row, fourier pairs, rel coords, B offsets ----
        for (int idx = tid; idx < EPAD; idx += 256) As[idx] = Ap[idx];
        if (tid < 32) {
            int e = tid;
            int j = g_knn[(size_t)node * KNN + e];
            ebo_s[e] = (uint32_t)(b * NNODES + j);
            float dx = cb[3 * i + 0] - cb[3 * j + 0];
            float dy = cb[3 * i + 1] - cb[3 * j + 1];
            float dz = cb[3 * i + 2] - cb[3 * j + 2];
            float d = dist2_f(dx, dy, dz);
            rc_s[e * 4 + 0] = dx; rc_s[e * 4 + 1] = dy; rc_s[e * 4 + 2] = dz; rc_s[e * 4 + 3] = 0.f;
            float s0, c0, s1, c1, s2, c2, s3, c3;
            sincosf(d,          &s0, &c0);
            sincosf(d * 0.5f,   &s1, &c1);
            sincosf(d * 0.25f,  &s2, &c2);
            sincosf(d * 0.125f, &s3, &c3);
            F2u[e * 6 + 0] = pack2(s0, s1);
            F2u[e * 6 + 1] = pack2(s2, s3);
            F2u[e * 6 + 2] = pack2(c0, c1);
            F2u[e * 6 + 3] = pack2(c2, c3);
            F2u[e * 6 + 4] = pack2(d, 0.f);
        }
        __syncthreads();

        // ---- registerize this warp's 4 edges' fourier (4 pairs + d each) ----
        int e0 = w * 4;
        ull fp0[4], fp1[4], fp2[4], fp3[4];
#pragma unroll
        for (int t = 0; t < 4; t++) {
            fp0[t] = F2u[(e0 + 0) * 6 + t];
            fp1[t] = F2u[(e0 + 1) * 6 + t];
            fp2[t] = F2u[(e0 + 2) * 6 + t];
            fp3[t] = F2u[(e0 + 3) * 6 + t];
        }
        const float* F2f = (const float*)F2u;
        float d0 = F2f[((e0 + 0) * 6 + 4) * 2];
        float d1 = F2f[((e0 + 1) * 6 + 4) * 2];
        float d2 = F2f[((e0 + 2) * 6 + 4) * 2];
        float d3 = F2f[((e0 + 3) * 6 + 4) * 2];

        const float* B0 = g_B + (size_t)ebo_s[e0 + 0] * EPAD;
        const float* B1 = g_B + (size_t)ebo_s[e0 + 1] * EPAD;
        const float* B2 = g_B + (size_t)ebo_s[e0 + 2] * EPAD;
        const float* B3 = g_B + (size_t)ebo_s[e0 + 3] * EPAD;
        const float* W9Bf = (const float*)W9B;

        ull m[32];   // [e*8+p]
#pragma unroll
        for (int p = 0; p < 32; p++) m[p] = 0ull;

#pragma unroll
        for (int it = 0; it < 17; it++) {
            int c = it * 32 + lane;
            float av = As[c];
            float bv0 = B0[c], bv1 = B1[c], bv2 = B2[c], bv3 = B3[c];
            ulonglong2 w9a0 = W9A[c * 2 + 0];
            ulonglong2 w9a1 = W9A[c * 2 + 1];
            float      w9b  = W9Bf[c * 2];

            // h chains (2 independent per edge, depth 2 + scalar seed)
            ull ha, hb; float2 hv;
            ha = pack2(fmaf(d0, w9b, av + bv0), 0.f); hb = 0ull;
            ffma2(ha, fp0[0], w9a0.x); ffma2(hb, fp0[1], w9a0.y);
            ffma2(ha, fp0[2], w9a1.x); ffma2(hb, fp0[3], w9a1.y);
            hv = unpack2(fadd2(ha, hb));
            float sh0 = silu_f(hv.x + hv.y);

            ha = pack2(fmaf(d1, w9b, av + bv1), 0.f); hb = 0ull;
            ffma2(ha, fp1[0], w9a0.x); ffma2(hb, fp1[1], w9a0.y);
            ffma2(ha, fp1[2], w9a1.x); ffma2(hb, fp1[3], w9a1.y);
            hv = unpack2(fadd2(ha, hb));
            float sh1 = silu_f(hv.x + hv.y);

            ha = pack2(fmaf(d2, w9b, av + bv2), 0.f); hb = 0ull;
            ffma2(ha, fp2[0], w9a0.x); ffma2(hb, fp2[1], w9a0.y);
            ffma2(ha, fp2[2], w9a1.x); ffma2(hb, fp2[3], w9a1.y);
            hv = unpack2(fadd2(ha, hb));
            float sh2 = silu_f(hv.x + hv.y);

            ha = pack2(fmaf(d3, w9b, av + bv3), 0.f); hb = 0ull;
            ffma2(ha, fp3[0], w9a0.x); ffma2(hb, fp3[1], w9a0.y);
            ffma2(ha, fp3[2], w9a1.x); ffma2(hb, fp3[3], w9a1.y);
            hv = unpack2(fadd2(ha, hb));
            float sh3 = silu_f(hv.x + hv.y);

            ull s0p = pack2(sh0, sh0);
            ull s1p = pack2(sh1, sh1);
            ull s2p = pack2(sh2, sh2);
            ull s3p = pack2(sh3, sh3);

            ulonglong2 q0 = We2q[c * 4 + 0];
            ulonglong2 q1 = We2q[c * 4 + 1];
            ulonglong2 q2 = We2q[c * 4 + 2];
            ulonglong2 q3 = We2q[c * 4 + 3];

            ffma2(m[0],  s0p, q0.x); ffma2(m[1],  s0p, q0.y);
            ffma2(m[2],  s0p, q1.x); ffma2(m[3],  s0p, q1.y);
            ffma2(m[4],  s0p, q2.x); ffma2(m[5],  s0p, q2.y);
            ffma2(m[6],  s0p, q3.x); ffma2(m[7],  s0p, q3.y);

            ffma2(m[8],  s1p, q0.x); ffma2(m[9],  s1p, q0.y);
            ffma2(m[10], s1p, q1.x); ffma2(m[11], s1p, q1.y);
            ffma2(m[12], s1p, q2.x); ffma2(m[13], s1p, q2.y);
            ffma2(m[14], s1p, q3.x); ffma2(m[15], s1p, q3.y);

            ffma2(m[16], s2p, q0.x); ffma2(m[17], s2p, q0.y);
            ffma2(m[18], s2p, q1.x); ffma2(m[19], s2p, q1.y);
            ffma2(m[20], s2p, q2.x); ffma2(m[21], s2p, q2.y);
            ffma2(m[22], s2p, q3.x); ffma2(m[23], s2p, q3.y);

            ffma2(m[24], s3p, q0.x); ffma2(m[25], s3p, q0.y);
            ffma2(m[26], s3p, q1.x); ffma2(m[27], s3p, q1.y);
            ffma2(m[28], s3p, q2.x); ffma2(m[29], s3p, q2.y);
            ffma2(m[30], s3p, q3.x); ffma2(m[31], s3p, q3.y);
        }

        // ---- reduce-scatter 32 f32x2 over 32 lanes -> lane l owns index l ----
        {
            bool up;
            up = (lane & 16);
#pragma unroll
            for (int v = 0; v < 16; v++) {
                ull give = up ? m[v] : m[v + 16];
                ull recv = __shfl_xor_sync(FULL, give, 16);
                ull keep = up ? m[v + 16] : m[v];
                m[v] = fadd2(keep, recv);
            }
            up = (lane & 8);
#pragma unroll
            for (int v = 0; v < 8; v++) {
                ull give = up ? m[v] : m[v + 8];
                ull recv = __shfl_xor_sync(FULL, give, 8);
                ull keep = up ? m[v + 8] : m[v];
                m[v] = fadd2(keep, recv);
            }
            up = (lane & 4);
#pragma unroll
            for (int v = 0; v < 4; v++) {
                ull give = up ? m[v] : m[v + 4];
                ull recv = __shfl_xor_sync(FULL, give, 4);
                ull keep = up ? m[v + 4] : m[v];
                m[v] = fadd2(keep, recv);
            }
            up = (lane & 2);
#pragma unroll
            for (int v = 0; v < 2; v++) {
                ull give = up ? m[v] : m[v + 2];
                ull recv = __shfl_xor_sync(FULL, give, 2);
                ull keep = up ? m[v + 2] : m[v];
                m[v] = fadd2(keep, recv);
            }
            up = (lane & 1);
            {
                ull give = up ? m[0] : m[1];
                ull recv = __shfl_xor_sync(FULL, give, 1);
                ull keep = up ? m[1] : m[0];
                m[0] = fadd2(keep, recv);
            }
            // lane l holds summed m[v=l]: e = e0 + (l>>3), k = 2*(l&7), 2*(l&7)+1
            float2 v2 = unpack2(m[0]);
            int e = e0 + (lane >> 3), k = 2 * (lane & 7);
            ms[e * 16 + k + 0] = silu_f(v2.x + be2s[k + 0]);
            ms[e * 16 + k + 1] = silu_f(v2.y + be2s[k + 1]);
        }
        __syncthreads();

        // ---- coors MLP: 8 threads per edge ----
        {
            int e = tid >> 3, li = tid & 7;
            float wpart = 0.f;
#pragma unroll
            for (int q = 0; q < 8; q++) {
                int l = li * 8 + q;
                float u = bc1s[l];
#pragma unroll
                for (int k = 0; k < 16; k++)
                    u = fmaf(ms[e * 16 + k], Wc1s[k * 64 + l], u);
                wpart = fmaf(silu_f(u), Wc2s[l], wpart);
            }
            wpart += __shfl_xor_sync(FULL, wpart, 1);
            wpart += __shfl_xor_sync(FULL, wpart, 2);
            wpart += __shfl_xor_sync(FULL, wpart, 4);
            if (li == 0) cw_s[e] = wpart + bc2v;
        }
        __syncthreads();

        // ---- m_i (threads 0-15) and coors_out (warp 1) ----
        if (tid < 16) {
            float s = 0.f;
#pragma unroll 8
            for (int e2 = 0; e2 < 32; e2++) s += ms[e2 * 16 + tid];
            g_XC[(size_t)node * 144 + 128 + tid] = s;
        }
        if (w == 1) {
            int e2 = lane;
            float wv = cw_s[e2];
            float px = wv * rc_s[e2 * 4 + 0];
            float py = wv * rc_s[e2 * 4 + 1];
            float pz = wv * rc_s[e2 * 4 + 2];
#pragma unroll
            for (int off = 16; off > 0; off >>= 1) {
                px += __shfl_down_sync(FULL, px, off);
                py += __shfl_down_sync(FULL, py, off);
                pz += __shfl_down_sync(FULL, pz, off);
            }
            if (lane == 0) {
                float* co = coors_out + (size_t)node * 3;
                co[0] = cb[3 * i + 0] + px;
                co[1] = cb[3 * i + 1] + py;
                co[2] = cb[3 * i + 2] + pz;
            }
        }
        __syncthreads();
    }
}

// ---------------------------------------------------------------------------
extern "C" void kernel_launch(void* const* d_in, const int* in_sizes, int n_in,
                              void* d_out, int out_size) {
    const float* feats = (const float*)d_in[0];
    const float* coors = (const float*)d_in[1];
    const float* We1   = (const float*)d_in[2];
    const float* be1   = (const float*)d_in[3];
    const float* We2   = (const float*)d_in[4];
    const float* be2   = (const float*)d_in[5];
    const float* Wc1   = (const float*)d_in[6];
    const float* bc1   = (const float*)d_in[7];
    const float* Wc2   = (const float*)d_in[8];
    const float* bc2   = (const float*)d_in[9];
    const float* Wn1   = (const float*)d_in[10];
    const float* bn1   = (const float*)d_in[11];
    const float* Wn2   = (const float*)d_in[12];
    const float* bn2   = (const float*)d_in[13];
    float* out = (float*)d_out;
    float* node_out  = out;
    float* coors_out = out + NODE_OUT_ELEMS;

    float *pA, *pB, *pXC, *pH1;
    cudaGetSymbolAddress((void**)&pA, g_A);
    cudaGetSymbolAddress((void**)&pB, g_B);
    cudaGetSymbolAddress((void**)&pXC, g_XC);
    cudaGetSymbolAddress((void**)&pH1, g_H1);

    cudaFuncSetAttribute(edge_kernel, cudaFuncAttributeMaxDynamicSharedMemorySize, EK_SMEM_BYTES);

    // 1) KNN
    knn_kernel<<<NODES / 8, 256>>>(coors);

    // 2) A = feats @ We1[0:128,:] + be1 ; B = feats @ We1[128:256,:]  (pad->544)
    gemm_kernel<<<dim3(9, NODES / 64), 256>>>(feats, DIMF, We1, HID, be1, nullptr, 0,
                                              pA, EPAD, HID, EPAD, DIMF, 0);
    gemm_kernel<<<dim3(9, NODES / 64), 256>>>(feats, DIMF, We1 + 128 * HID, HID, nullptr, nullptr, 0,
                                              pB, EPAD, HID, EPAD, DIMF, 0);

    // 3) edges: m_ij -> m_i (XC[:,128:144]), coors_out
    edge_kernel<<<NODES / 4, 256, EK_SMEM_BYTES>>>(coors, We1, We2, be2,
                                                   Wc1, bc1, Wc2, bc2, coors_out);

    // 4) XC[:, 0:128] = feats
    copy_feats_kernel<<<(NODES * DIMF) / 256, 256>>>(feats);

    // 5) node MLP
    gemm_kernel<<<dim3(4, NODES / 64), 256>>>(pXC, 144, Wn1, 256, bn1, nullptr, 0,
                                              pH1, 256, 256, 256, 144, 1);
    gemm_kernel<<<dim3(2, NODES / 64), 256>>>(pH1, 256, Wn2, DIMF, bn2, feats, DIMF,
                                              node_out, DIMF, DIMF, DIMF, 256, 0);
}

// round 12
// speedup vs baseline: 1.2496x; 1.2496x over previous
#include <cuda_runtime.h>
#include <cuda_bf16.h>
#include <math.h>
#include <stdint.h>

#define BB 2
#define NNODES 4096
#define DIMF 128
#define KNN 32
#define HID 530
#define EPAD 544                    // padded hidden (4*128 + 32)
#define NODES (BB*NNODES)           // 8192
#define NODE_OUT_ELEMS (NODES*DIMF)

typedef unsigned long long ull;

// ---------------- scratch (static device arrays; no allocation) -------------
__device__ float g_A[NODES * EPAD];    // feats@We1[0:128]+be1 (pad cols zero)
__device__ float g_B[NODES * EPAD];    // feats@We1[128:256]   (pad cols zero)
__device__ float g_XC[NODES * 144];    // [feats | m_i]
__device__ float g_H1[NODES * 256];    // node hidden
__device__ int   g_knn[NODES * KNN];

// ---------------- f32x2 helpers ---------------------------------------------
__device__ __forceinline__ ull pack2(float lo, float hi) {
    ull u; asm("mov.b64 %0, {%1, %2};" : "=l"(u) : "f"(lo), "f"(hi)); return u;
}
__device__ __forceinline__ float2 unpack2(ull u) {
    float2 v; asm("mov.b64 {%0, %1}, %2;" : "=f"(v.x), "=f"(v.y) : "l"(u)); return v;
}
__device__ __forceinline__ void ffma2(ull& d, ull a, ull b) {
    asm("fma.rn.f32x2 %0, %1, %2, %0;" : "+l"(d) : "l"(a), "l"(b));
}
__device__ __forceinline__ ull fadd2(ull a, ull b) {
    ull d; asm("add.rn.f32x2 %0, %1, %2;" : "=l"(d) : "l"(a), "l"(b)); return d;
}

__device__ __forceinline__ float silu_f(float x) {
    float e = __expf(-x);
    return __fdividef(x, 1.0f + e);
}

__device__ __forceinline__ float dist2_f(float dx, float dy, float dz) {
    return __fadd_rn(__fadd_rn(__fmul_rn(dx, dx), __fmul_rn(dy, dy)), __fmul_rn(dz, dz));
}

// ---------------------------------------------------------------------------
// KNN: one warp per (b,i). Unsorted top-32 set via warp REDUX threshold.
// ---------------------------------------------------------------------------
__global__ __launch_bounds__(256) void knn_kernel(const float* __restrict__ coors) {
    const unsigned FULL = 0xffffffffu;
    int w    = blockIdx.x * 8 + (threadIdx.x >> 5);
    int lane = threadIdx.x & 31;
    int b = w >> 12;
    int i = w & (NNODES - 1);
    const float* cb = coors + (size_t)b * NNODES * 3;
    float qx = cb[3 * i + 0], qy = cb[3 * i + 1], qz = cb[3 * i + 2];

    float dx = qx - cb[3 * lane + 0];
    float dy = qy - cb[3 * lane + 1];
    float dz = qz - cb[3 * lane + 2];
    unsigned bu = __float_as_uint(dist2_f(dx, dy, dz));
    int bj = lane;
    unsigned curmax = __reduce_max_sync(FULL, bu);

    for (int j0 = 32; j0 < NNODES; j0 += 32) {
        int j = j0 + lane;
        float ex = qx - cb[3 * j + 0];
        float ey = qy - cb[3 * j + 1];
        float ez = qz - cb[3 * j + 2];
        unsigned du = __float_as_uint(dist2_f(ex, ey, ez));
        unsigned mask = __ballot_sync(FULL, du < curmax);
        while (mask) {
            int src = __ffs(mask) - 1;
            mask &= mask - 1;
            unsigned dc = __shfl_sync(FULL, du, src);
            if (dc < curmax) {
                unsigned mm = __ballot_sync(FULL, bu == curmax);
                int ml = __ffs(mm) - 1;
                if (lane == ml) { bu = dc; bj = j0 + src; }
                curmax = __reduce_max_sync(FULL, bu);
            }
        }
    }
    g_knn[(size_t)w * KNN + lane] = bj;
}

// ---------------------------------------------------------------------------
// Tiled fp32 GEMM (FFMA2): C[.. x Npad] = act(X @ W + b) (+resid); pads -> 0
// ---------------------------------------------------------------------------
__global__ __launch_bounds__(256) void gemm_kernel(
    const float* __restrict__ X, int ldx,
    const float* __restrict__ W, int ldw,
    const float* __restrict__ bias,
    const float* __restrict__ resid, int ldr,
    float* __restrict__ C, int ldc,
    int Nw, int Npad, int K, int act)
{
    __shared__ float Xs[16][68];
    __shared__ float Ws[16][68];
    int tid = threadIdx.x;
    int tx = tid & 15, ty = tid >> 4;
    int m0 = blockIdx.y * 64, n0 = blockIdx.x * 64;

    int lm  = tid >> 2;
    int lk  = (tid & 3) * 4;
    int wn  = tid & 63;
    int wkb = (tid >> 6) * 4;

    ull acc2[4][2];
#pragma unroll
    for (int a = 0; a < 4; a++) { acc2[a][0] = 0ull; acc2[a][1] = 0ull; }

    for (int kt = 0; kt < K; kt += 16) {
        float4 xv = *reinterpret_cast<const float4*>(X + (size_t)(m0 + lm) * ldx + kt + lk);
        Xs[lk + 0][lm] = xv.x;
        Xs[lk + 1][lm] = xv.y;
        Xs[lk + 2][lm] = xv.z;
        Xs[lk + 3][lm] = xv.w;
#pragma unroll
        for (int q = 0; q < 4; q++) {
            int k = wkb + q;
            float v = (n0 + wn < Nw) ? W[(size_t)(kt + k) * ldw + n0 + wn] : 0.f;
            Ws[k][wn] = v;
        }
        __syncthreads();
#pragma unroll
        for (int k = 0; k < 16; k++) {
            float4 a4 = *reinterpret_cast<const float4*>(&Xs[k][ty * 4]);
            float4 b4 = *reinterpret_cast<const float4*>(&Ws[k][tx * 4]);
            ull b01 = pack2(b4.x, b4.y);
            ull b23 = pack2(b4.z, b4.w);
            float av[4] = {a4.x, a4.y, a4.z, a4.w};
#pragma unroll
            for (int mi = 0; mi < 4; mi++) {
                ull aa = pack2(av[mi], av[mi]);
                ffma2(acc2[mi][0], aa, b01);
                ffma2(acc2[mi][1], aa, b23);
            }
        }
        __syncthreads();
    }

#pragma unroll
    for (int mi = 0; mi < 4; mi++) {
        int m = m0 + ty * 4 + mi;
        float2 lo = unpack2(acc2[mi][0]);
        float2 hi = unpack2(acc2[mi][1]);
        float accv[4] = {lo.x, lo.y, hi.x, hi.y};
#pragma unroll
        for (int ni = 0; ni < 4; ni++) {
            int n = n0 + tx * 4 + ni;
            if (n < Npad) {
                float v = accv[ni];
                if (n < Nw) {
                    if (bias) v += bias[n];
                    if (act) v = silu_f(v);
                    if (resid) v += resid[(size_t)m * ldr + n];
                } else {
                    v = 0.f;
                }
                C[(size_t)m * ldc + n] = v;
            }
        }
    }
}

// ---------------------------------------------------------------------------
__global__ __launch_bounds__(256) void copy_feats_kernel(const float* __restrict__ feats) {
    int idx = blockIdx.x * 256 + threadIdx.x;  // over NODES*128
    int n = idx >> 7, c = idx & 127;
    g_XC[(size_t)n * 144 + c] = feats[idx];
}

// ---------------------------------------------------------------------------
// Edge kernel v4 (two-phase): 256 threads, 8 warps, 4 nodes/block, 3 blk/SM.
// Per node, per 128-channel chunk:
//   P1: warp w -> edges 4w..4w+3, lanes stride channels: compute sh = silu(h),
//       store into pair-major SHP[(c/2)*68 + e*2 + (c&1)].
//   P2: k-sliced GEMM: lane (eg=lane>>2, og=lane&3) accumulates the 4x4
//       micro-tile [edges eg*4+ei][outs og*4+oi] over this warp's pair-slice,
//       reading sh-pairs and We2-pairs as ulonglong2 (all FFMA2).
// Tree reduction across warps; epilogue (coors MLP, m_i, coors_out) as R7.
// ---------------------------------------------------------------------------
#define OFF_WE2PP 0                               // ull[272][16]      = 34816
#define OFF_W9A   34816                           // ulonglong2[544*2] = 17408
#define OFF_W9B   52224                           // float[544]        = 2176
#define OFF_SHR   54400                           // 17408 (SHP / tree / ms / cw / Wc1)
#define OFF_FLT   71808
// FLT float indices:
#define FI_BC1 0
#define FI_WC2 64
#define FI_BE2 128
#define FI_RC  144
#define FI_EBO 272
#define FI_F2  304                                // ull[32*6] (8B aligned: 304*4=1216)
#define FI_TOT (304 + 192*2)                      // 688 floats = 2752 B
#define EK_SMEM_BYTES (OFF_FLT + FI_TOT*4)        // 74560
// SHR-internal float offsets:
#define SHR_MS  2048                              // byte 8192
#define SHR_CW  2560                              // byte 10240
#define SHR_WC1 2592                              // byte 10368

__global__ __launch_bounds__(256, 3) void edge_kernel(
    const float* __restrict__ coors,
    const float* __restrict__ We1,
    const float* __restrict__ We2,
    const float* __restrict__ be2,
    const float* __restrict__ Wc1,
    const float* __restrict__ bc1,
    const float* __restrict__ Wc2,
    const float* __restrict__ bc2,
    float* __restrict__ coors_out)
{
    extern __shared__ char smc[];
    ull* We2pp = (ull*)(smc + OFF_WE2PP);
    ulonglong2* W9A = (ulonglong2*)(smc + OFF_W9A);
    float* W9Bf = (float*)(smc + OFF_W9B);
    float* SHR  = (float*)(smc + OFF_SHR);
    float* smf  = (float*)(smc + OFF_FLT);
    float* bc1s = smf + FI_BC1;
    float* Wc2s = smf + FI_WC2;
    float* be2s = smf + FI_BE2;
    float* rc_s = smf + FI_RC;                    // [32][4]
    uint32_t* ebo_s = (uint32_t*)(smf + FI_EBO);  // [32]
    ull* F2u = (ull*)(smf + FI_F2);               // [32][6]
    float* msp  = SHR + SHR_MS;                   // [32][16]
    float* cwp  = SHR + SHR_CW;                   // [32]
    float* Wc1p = SHR + SHR_WC1;                  // [16][64]

    int tid = threadIdx.x;
    int w = tid >> 5, lane = tid & 31;
    const unsigned FULL = 0xffffffffu;
    float bc2v = bc2[0];

    // ---- weight preamble (once per block) ----
    for (int idx = tid; idx < 272 * 16; idx += 256) {
        int c2 = idx >> 4, o = idx & 15;
        float lo = (2 * c2     < HID) ? We2[(2 * c2)     * 16 + o] : 0.f;
        float hi = (2 * c2 + 1 < HID) ? We2[(2 * c2 + 1) * 16 + o] : 0.f;
        We2pp[idx] = pack2(lo, hi);
    }
    for (int idx = tid; idx < 2 * EPAD; idx += 256) {
        int c = idx >> 1, t = idx & 1;
        ulonglong2 v; v.x = 0ull; v.y = 0ull;
        if (c < HID) {
            v.x = pack2(We1[(size_t)(256 + 4 * t + 0) * HID + c], We1[(size_t)(256 + 4 * t + 1) * HID + c]);
            v.y = pack2(We1[(size_t)(256 + 4 * t + 2) * HID + c], We1[(size_t)(256 + 4 * t + 3) * HID + c]);
        }
        W9A[idx] = v;
    }
    for (int c = tid; c < EPAD; c += 256)
        W9Bf[c] = (c < HID) ? We1[(size_t)264 * HID + c] : 0.f;
    if (tid < 64) { bc1s[tid] = bc1[tid]; Wc2s[tid] = Wc2[tid]; }
    if (tid >= 64 && tid < 80) be2s[tid - 64] = be2[tid - 64];
    __syncthreads();

#pragma unroll 1
    for (int nn = 0; nn < 4; nn++) {
        int node = blockIdx.x * 4 + nn;
        int b = node >> 12, i = node & (NNODES - 1);
        const float* cb = coors + (size_t)b * NNODES * 3;
        size_t aoff = (size_t)node * EPAD;

        // ---- setup (tid<32): knn, rel coords, fourier pairs ----
        if (tid < 32) {
            int e = tid;
            int j = g_knn[(size_t)node * KNN + e];
            ebo_s[e] = (uint32_t)(b * NNODES + j);
            float dx = cb[3 * i + 0] - cb[3 * j + 0];
            float dy = cb[3 * i + 1] - cb[3 * j + 1];
            float dz = cb[3 * i + 2] - cb[3 * j + 2];
            float d = dist2_f(dx, dy, dz);
            rc_s[e * 4 + 0] = dx; rc_s[e * 4 + 1] = dy; rc_s[e * 4 + 2] = dz; rc_s[e * 4 + 3] = 0.f;
            float s0, c0, s1, c1, s2, c2, s3, c3;
            sincosf(d,          &s0, &c0);
            sincosf(d * 0.5f,   &s1, &c1);
            sincosf(d * 0.25f,  &s2, &c2);
            sincosf(d * 0.125f, &s3, &c3);
            F2u[e * 6 + 0] = pack2(s0, s1);
            F2u[e * 6 + 1] = pack2(s2, s3);
            F2u[e * 6 + 2] = pack2(c0, c1);
            F2u[e * 6 + 3] = pack2(c2, c3);
            F2u[e * 6 + 4] = pack2(d, 0.f);
        }
        __syncthreads();

        int e0 = w * 4;
        int eg = lane >> 2, og = lane & 3;
        uint32_t brow0 = ebo_s[e0 + 0], brow1 = ebo_s[e0 + 1];
        uint32_t brow2 = ebo_s[e0 + 2], brow3 = ebo_s[e0 + 3];

        float m16[16];
#pragma unroll
        for (int p = 0; p < 16; p++) m16[p] = 0.f;

#pragma unroll 1
        for (int chunk = 0; chunk < 5; chunk++) {
            int nch = (chunk < 4) ? 128 : 32;
            int cbase = chunk * 128;

            // ---- P1: produce sh for this warp's 4 edges over the chunk ----
            {
                // fourier registers (reload per chunk keeps live ranges short)
                ull fpa[4][4]; float dd[4];
#pragma unroll
                for (int q = 0; q < 4; q++) {
#pragma unroll
                    for (int t = 0; t < 4; t++) fpa[q][t] = F2u[(e0 + q) * 6 + t];
                    dd[q] = ((const float*)&F2u[(e0 + q) * 6 + 4])[0];
                }
                int niter = nch >> 5;
#pragma unroll
                for (int it = 0; it < 4; it++) {
                    if (it >= niter) break;
                    int cl = it * 32 + lane;
                    int c = cbase + cl;
                    float av = g_A[aoff + c];
                    float bv[4];
                    bv[0] = g_B[(size_t)brow0 * EPAD + c];
                    bv[1] = g_B[(size_t)brow1 * EPAD + c];
                    bv[2] = g_B[(size_t)brow2 * EPAD + c];
                    bv[3] = g_B[(size_t)brow3 * EPAD + c];
                    ulonglong2 w9a0 = W9A[c * 2 + 0];
                    ulonglong2 w9a1 = W9A[c * 2 + 1];
                    float      w9b  = W9Bf[c];
                    int sbase = (cl >> 1) * 68 + (cl & 1);
#pragma unroll
                    for (int q = 0; q < 4; q++) {
                        ull ha = pack2(fmaf(dd[q], w9b, av + bv[q]), 0.f);
                        ull hb = 0ull;
                        ffma2(ha, fpa[q][0], w9a0.x);
                        ffma2(hb, fpa[q][1], w9a0.y);
                        ffma2(ha, fpa[q][2], w9a1.x);
                        ffma2(hb, fpa[q][3], w9a1.y);
                        float2 hv = unpack2(fadd2(ha, hb));
                        SHR[sbase + (e0 + q) * 2] = silu_f(hv.x + hv.y);
                    }
                }
            }
            __syncthreads();

            // ---- P2: k-sliced 32x16 GEMM on this chunk ----
            {
                int npair = nch >> 1;
                int ppw = npair >> 3;          // 8 (big chunks) or 2 (tail)
                ull macc[16];
#pragma unroll
                for (int p = 0; p < 16; p++) macc[p] = 0ull;

                int c2b = w * ppw;
#pragma unroll
                for (int p = 0; p < 8; p++) {
                    if (p >= ppw) break;
                    int c2 = c2b + p;
                    int c2g = chunk * 64 + c2;
                    ulonglong2 sA = *(const ulonglong2*)(SHR + c2 * 68 + eg * 8);
                    ulonglong2 sB = *(const ulonglong2*)(SHR + c2 * 68 + eg * 8 + 4);
                    ulonglong2 u01 = *(const ulonglong2*)(We2pp + c2g * 16 + og * 4);
                    ulonglong2 u23 = *(const ulonglong2*)(We2pp + c2g * 16 + og * 4 + 2);

                    ffma2(macc[0],  sA.x, u01.x); ffma2(macc[1],  sA.x, u01.y);
                    ffma2(macc[2],  sA.x, u23.x); ffma2(macc[3],  sA.x, u23.y);
                    ffma2(macc[4],  sA.y, u01.x); ffma2(macc[5],  sA.y, u01.y);
                    ffma2(macc[6],  sA.y, u23.x); ffma2(macc[7],  sA.y, u23.y);
                    ffma2(macc[8],  sB.x, u01.x); ffma2(macc[9],  sB.x, u01.y);
                    ffma2(macc[10], sB.x, u23.x); ffma2(macc[11], sB.x, u23.y);
                    ffma2(macc[12], sB.y, u01.x); ffma2(macc[13], sB.y, u01.y);
                    ffma2(macc[14], sB.y, u23.x); ffma2(macc[15], sB.y, u23.y);
                }
#pragma unroll
                for (int p = 0; p < 16; p++) {
                    float2 v = unpack2(macc[p]);
                    m16[p] += v.x + v.y;
                }
            }
            __syncthreads();   // SHP consumed; next chunk's P1 may overwrite
        }

        // ---- tree reduction across 8 warps ----
        // lane (eg,og) holds m16[ei*4+oi] for edge eg*4+ei, out og*4+oi
#pragma unroll 1
        for (int step = 0; step < 3; step++) {
            int half = 4 >> step;              // 4, 2, 1
            if (w >= half && w < 2 * half) {
#pragma unroll
                for (int ei = 0; ei < 4; ei++) {
                    float4 v = make_float4(m16[ei * 4 + 0], m16[ei * 4 + 1],
                                           m16[ei * 4 + 2], m16[ei * 4 + 3]);
                    *(float4*)(SHR + (w - half) * 512 + (eg * 4 + ei) * 16 + og * 4) = v;
                }
            }
            __syncthreads();
            if (w < half) {
#pragma unroll
                for (int ei = 0; ei < 4; ei++) {
                    float4 v = *(const float4*)(SHR + w * 512 + (eg * 4 + ei) * 16 + og * 4);
                    m16[ei * 4 + 0] += v.x; m16[ei * 4 + 1] += v.y;
                    m16[ei * 4 + 2] += v.z; m16[ei * 4 + 3] += v.w;
                }
            }
            __syncthreads();
        }
        if (w == 0) {
#pragma unroll
            for (int ei = 0; ei < 4; ei++)
#pragma unroll
                for (int oi = 0; oi < 4; oi++) {
                    int k = og * 4 + oi;
                    msp[(eg * 4 + ei) * 16 + k] = silu_f(m16[ei * 4 + oi] + be2s[k]);
                }
        }
        // Wc1 reload (clobbered by SHP each node)
        {
            float4 v = *(const float4*)(Wc1 + tid * 4);
            *(float4*)(Wc1p + tid * 4) = v;
        }
        __syncthreads();

        // ---- coors MLP: 8 threads per edge ----
        {
            int e = tid >> 3, li = tid & 7;
            float wpart = 0.f;
#pragma unroll
            for (int q = 0; q < 8; q++) {
                int l = li * 8 + q;
                float u = bc1s[l];
#pragma unroll
                for (int k = 0; k < 16; k++)
                    u = fmaf(msp[e * 16 + k], Wc1p[k * 64 + l], u);
                wpart = fmaf(silu_f(u), Wc2s[l], wpart);
            }
            wpart += __shfl_xor_sync(FULL, wpart, 1);
            wpart += __shfl_xor_sync(FULL, wpart, 2);
            wpart += __shfl_xor_sync(FULL, wpart, 4);
            if (li == 0) cwp[e] = wpart + bc2v;
        }
        __syncthreads();

        // ---- m_i (threads 0-15) and coors_out (warp 1) ----
        if (tid < 16) {
            float s = 0.f;
#pragma unroll 8
            for (int e2 = 0; e2 < 32; e2++) s += msp[e2 * 16 + tid];
            g_XC[(size_t)node * 144 + 128 + tid] = s;
        }
        if (w == 1) {
            int e2 = lane;
            float wv = cwp[e2];
            float px = wv * rc_s[e2 * 4 + 0];
            float py = wv * rc_s[e2 * 4 + 1];
            float pz = wv * rc_s[e2 * 4 + 2];
#pragma unroll
            for (int off = 16; off > 0; off >>= 1) {
                px += __shfl_down_sync(FULL, px, off);
                py += __shfl_down_sync(FULL, py, off);
                pz += __shfl_down_sync(FULL, pz, off);
            }
            if (e2 == 0) {
                float* co = coors_out + (size_t)node * 3;
                co[0] = cb[3 * i + 0] + px;
                co[1] = cb[3 * i + 1] + py;
                co[2] = cb[3 * i + 2] + pz;
            }
        }
        __syncthreads();
    }
}

// ---------------------------------------------------------------------------
extern "C" void kernel_launch(void* const* d_in, const int* in_sizes, int n_in,
                              void* d_out, int out_size) {
    const float* feats = (const float*)d_in[0];
    const float* coors = (const float*)d_in[1];
    const float* We1   = (const float*)d_in[2];
    const float* be1   = (const float*)d_in[3];
    const float* We2   = (const float*)d_in[4];
    const float* be2   = (const float*)d_in[5];
    const float* Wc1   = (const float*)d_in[6];
    const float* bc1   = (const float*)d_in[7];
    const float* Wc2   = (const float*)d_in[8];
    const float* bc2   = (const float*)d_in[9];
    const float* Wn1   = (const float*)d_in[10];
    const float* bn1   = (const float*)d_in[11];
    const float* Wn2   = (const float*)d_in[12];
    const float* bn2   = (const float*)d_in[13];
    float* out = (float*)d_out;
    float* node_out  = out;
    float* coors_out = out + NODE_OUT_ELEMS;

    float *pA, *pB, *pXC, *pH1;
    cudaGetSymbolAddress((void**)&pA, g_A);
    cudaGetSymbolAddress((void**)&pB, g_B);
    cudaGetSymbolAddress((void**)&pXC, g_XC);
    cudaGetSymbolAddress((void**)&pH1, g_H1);

    cudaFuncSetAttribute(edge_kernel, cudaFuncAttributeMaxDynamicSharedMemorySize, EK_SMEM_BYTES);

    // 1) KNN
    knn_kernel<<<NODES / 8, 256>>>(coors);

    // 2) A = feats @ We1[0:128,:] + be1 ; B = feats @ We1[128:256,:]  (pad->544)
    gemm_kernel<<<dim3(9, NODES / 64), 256>>>(feats, DIMF, We1, HID, be1, nullptr, 0,
                                              pA, EPAD, HID, EPAD, DIMF, 0);
    gemm_kernel<<<dim3(9, NODES / 64), 256>>>(feats, DIMF, We1 + 128 * HID, HID, nullptr, nullptr, 0,
                                              pB, EPAD, HID, EPAD, DIMF, 0);

    // 3) edges: m_ij -> m_i (XC[:,128:144]), coors_out
    edge_kernel<<<NODES / 4, 256, EK_SMEM_BYTES>>>(coors, We1, We2, be2,
                                                   Wc1, bc1, Wc2, bc2, coors_out);

    // 4) XC[:, 0:128] = feats
    copy_feats_kernel<<<(NODES * DIMF) / 256, 256>>>(feats);

    // 5) node MLP
    gemm_kernel<<<dim3(4, NODES / 64), 256>>>(pXC, 144, Wn1, 256, bn1, nullptr, 0,
                                              pH1, 256, 256, 256, 144, 1);
    gemm_kernel<<<dim3(2, NODES / 64), 256>>>(pH1, 256, Wn2, DIMF, bn2, feats, DIMF,
                                              node_out, DIMF, DIMF, DIMF, 256, 0);
}

// round 13
// speedup vs baseline: 1.3070x; 1.0460x over previous
#include <cuda_runtime.h>
#include <cuda_bf16.h>
#include <math.h>
#include <stdint.h>

#define BB 2
#define NNODES 4096
#define DIMF 128
#define KNN 32
#define HID 530
#define EPAD 544                    // padded hidden (17*32)
#define NODES (BB*NNODES)           // 8192
#define NODE_OUT_ELEMS (NODES*DIMF)

typedef unsigned long long ull;

// ---------------- scratch (static device arrays; no allocation) -------------
__device__ float g_A[NODES * EPAD];    // feats@We1[0:128]+be1 (pad cols zero)
__device__ float g_B[NODES * EPAD];    // feats@We1[128:256]   (pad cols zero)
__device__ float g_XC[NODES * 144];    // [feats | m_i]
__device__ float g_H1[NODES * 256];    // node hidden
__device__ int   g_knn[NODES * KNN];

// ---------------- f32x2 helpers ---------------------------------------------
__device__ __forceinline__ ull pack2(float lo, float hi) {
    ull u; asm("mov.b64 %0, {%1, %2};" : "=l"(u) : "f"(lo), "f"(hi)); return u;
}
__device__ __forceinline__ float2 unpack2(ull u) {
    float2 v; asm("mov.b64 {%0, %1}, %2;" : "=f"(v.x), "=f"(v.y) : "l"(u)); return v;
}
__device__ __forceinline__ void ffma2(ull& d, ull a, ull b) {
    asm("fma.rn.f32x2 %0, %1, %2, %0;" : "+l"(d) : "l"(a), "l"(b));
}
__device__ __forceinline__ ull fadd2(ull a, ull b) {
    ull d; asm("add.rn.f32x2 %0, %1, %2;" : "=l"(d) : "l"(a), "l"(b)); return d;
}

__device__ __forceinline__ float silu_f(float x) {
    float e = __expf(-x);
    return __fdividef(x, 1.0f + e);
}

__device__ __forceinline__ float dist2_f(float dx, float dy, float dz) {
    return __fadd_rn(__fadd_rn(__fmul_rn(dx, dx), __fmul_rn(dy, dy)), __fmul_rn(dz, dz));
}

__device__ __forceinline__ uint32_t smem_u32(const void* p) {
    uint32_t a;
    asm("{ .reg .u64 t; cvta.to.shared.u64 t, %1; cvt.u32.u64 %0, t; }" : "=r"(a) : "l"(p));
    return a;
}

__device__ __forceinline__ uint32_t bf16x2_pack(float lo, float hi) {
    uint32_t r;
    asm("cvt.rn.bf16x2.f32 %0, %1, %2;" : "=r"(r) : "f"(hi), "f"(lo));
    return r;
}

// ---------------------------------------------------------------------------
// KNN: one warp per (b,i). Unsorted top-32 set via warp REDUX threshold.
// ---------------------------------------------------------------------------
__global__ __launch_bounds__(256) void knn_kernel(const float* __restrict__ coors) {
    const unsigned FULL = 0xffffffffu;
    int w    = blockIdx.x * 8 + (threadIdx.x >> 5);
    int lane = threadIdx.x & 31;
    int b = w >> 12;
    int i = w & (NNODES - 1);
    const float* cb = coors + (size_t)b * NNODES * 3;
    float qx = cb[3 * i + 0], qy = cb[3 * i + 1], qz = cb[3 * i + 2];

    float dx = qx - cb[3 * lane + 0];
    float dy = qy - cb[3 * lane + 1];
    float dz = qz - cb[3 * lane + 2];
    unsigned bu = __float_as_uint(dist2_f(dx, dy, dz));
    int bj = lane;
    unsigned curmax = __reduce_max_sync(FULL, bu);

    for (int j0 = 32; j0 < NNODES; j0 += 32) {
        int j = j0 + lane;
        float ex = qx - cb[3 * j + 0];
        float ey = qy - cb[3 * j + 1];
        float ez = qz - cb[3 * j + 2];
        unsigned du = __float_as_uint(dist2_f(ex, ey, ez));
        unsigned mask = __ballot_sync(FULL, du < curmax);
        while (mask) {
            int src = __ffs(mask) - 1;
            mask &= mask - 1;
            unsigned dc = __shfl_sync(FULL, du, src);
            if (dc < curmax) {
                unsigned mm = __ballot_sync(FULL, bu == curmax);
                int ml = __ffs(mm) - 1;
                if (lane == ml) { bu = dc; bj = j0 + src; }
                curmax = __reduce_max_sync(FULL, bu);
            }
        }
    }
    g_knn[(size_t)w * KNN + lane] = bj;
}

// ---------------------------------------------------------------------------
// Tiled fp32 GEMM (FFMA2): C[.. x Npad] = act(X @ W + b) (+resid); pads -> 0
// ---------------------------------------------------------------------------
__global__ __launch_bounds__(256) void gemm_kernel(
    const float* __restrict__ X, int ldx,
    const float* __restrict__ W, int ldw,
    const float* __restrict__ bias,
    const float* __restrict__ resid, int ldr,
    float* __restrict__ C, int ldc,
    int Nw, int Npad, int K, int act)
{
    __shared__ float Xs[16][68];
    __shared__ float Ws[16][68];
    int tid = threadIdx.x;
    int tx = tid & 15, ty = tid >> 4;
    int m0 = blockIdx.y * 64, n0 = blockIdx.x * 64;

    int lm  = tid >> 2;
    int lk  = (tid & 3) * 4;
    int wn  = tid & 63;
    int wkb = (tid >> 6) * 4;

    ull acc2[4][2];
#pragma unroll
    for (int a = 0; a < 4; a++) { acc2[a][0] = 0ull; acc2[a][1] = 0ull; }

    for (int kt = 0; kt < K; kt += 16) {
        float4 xv = *reinterpret_cast<const float4*>(X + (size_t)(m0 + lm) * ldx + kt + lk);
        Xs[lk + 0][lm] = xv.x;
        Xs[lk + 1][lm] = xv.y;
        Xs[lk + 2][lm] = xv.z;
        Xs[lk + 3][lm] = xv.w;
#pragma unroll
        for (int q = 0; q < 4; q++) {
            int k = wkb + q;
            float v = (n0 + wn < Nw) ? W[(size_t)(kt + k) * ldw + n0 + wn] : 0.f;
            Ws[k][wn] = v;
        }
        __syncthreads();
#pragma unroll
        for (int k = 0; k < 16; k++) {
            float4 a4 = *reinterpret_cast<const float4*>(&Xs[k][ty * 4]);
            float4 b4 = *reinterpret_cast<const float4*>(&Ws[k][tx * 4]);
            ull b01 = pack2(b4.x, b4.y);
            ull b23 = pack2(b4.z, b4.w);
            float av[4] = {a4.x, a4.y, a4.z, a4.w};
#pragma unroll
            for (int mi = 0; mi < 4; mi++) {
                ull aa = pack2(av[mi], av[mi]);
                ffma2(acc2[mi][0], aa, b01);
                ffma2(acc2[mi][1], aa, b23);
            }
        }
        __syncthreads();
    }

#pragma unroll
    for (int mi = 0; mi < 4; mi++) {
        int m = m0 + ty * 4 + mi;
        float2 lo = unpack2(acc2[mi][0]);
        float2 hi = unpack2(acc2[mi][1]);
        float accv[4] = {lo.x, lo.y, hi.x, hi.y};
#pragma unroll
        for (int ni = 0; ni < 4; ni++) {
            int n = n0 + tx * 4 + ni;
            if (n < Npad) {
                float v = accv[ni];
                if (n < Nw) {
                    if (bias) v += bias[n];
                    if (act) v = silu_f(v);
                    if (resid) v += resid[(size_t)m * ldr + n];
                } else {
                    v = 0.f;
                }
                C[(size_t)m * ldc + n] = v;
            }
        }
    }
}

// ---------------------------------------------------------------------------
__global__ __launch_bounds__(256) void copy_feats_kernel(const float* __restrict__ feats) {
    int idx = blockIdx.x * 256 + threadIdx.x;  // over NODES*128
    int n = idx >> 7, c = idx & 127;
    g_XC[(size_t)n * 144 + c] = feats[idx];
}

// ---------------------------------------------------------------------------
// Edge kernel v5 (P1 fp32 scalar + P2 tensor-core mma.sync bf16):
// 256 threads, 8 warps, 4 nodes/block, 3 blocks/SM.
// P1: warp w -> edges 4w..4w+3, lanes stride channels; sh stored bf16 into
//     SHM[edge][136] (272B row stride, ldmatrix-friendly).
// P2: k-sliced tensor GEMM: warp w does k16-step w of each 128-ch chunk;
//     A frags via ldmatrix.x4, B (We2 bf16x2 pairs) via LDS.32, fp32 accum.
// Tree reduction of the 16 partial D floats across warps; epilogue as before.
// ---------------------------------------------------------------------------
#define OFF_WE2P  0                               // u32[272*16]       = 17408
#define OFF_W9A   17408                           // ulonglong2[544*2] = 17408
#define OFF_W9B   34816                           // float[544]        = 2176
#define OFF_SHM   36992                           // bf16[32][136] = 8704 (tree overlay)
#define OFF_WC1   45696                           // float[16][64]     = 4096
#define OFF_MS    49792                           // float[32][16]     = 2048
#define OFF_FLT   51840
#define FI_BC1 0
#define FI_WC2 64
#define FI_BE2 128
#define FI_RC  144
#define FI_CW  272
#define FI_EBO 304
#define FI_F2  336                                // ull[32*6]: byte off 51840+1344 = 53184 (8-aligned)
#define FI_TOT (336 + 384)
#define EK_SMEM_BYTES (OFF_FLT + FI_TOT*4)        // 54720

__global__ __launch_bounds__(256, 3) void edge_kernel(
    const float* __restrict__ coors,
    const float* __restrict__ We1,
    const float* __restrict__ We2,
    const float* __restrict__ be2,
    const float* __restrict__ Wc1,
    const float* __restrict__ bc1,
    const float* __restrict__ Wc2,
    const float* __restrict__ bc2,
    float* __restrict__ coors_out)
{
    extern __shared__ char smc[];
    uint32_t* We2p = (uint32_t*)(smc + OFF_WE2P);      // [k2][16] bf16x2 pairs
    ulonglong2* W9A = (ulonglong2*)(smc + OFF_W9A);
    float* W9Bf = (float*)(smc + OFF_W9B);
    __nv_bfloat16* SHM16 = (__nv_bfloat16*)(smc + OFF_SHM);
    float* SHRf = (float*)(smc + OFF_SHM);             // tree-reduce overlay
    float* Wc1s = (float*)(smc + OFF_WC1);
    float* msp  = (float*)(smc + OFF_MS);
    float* smf  = (float*)(smc + OFF_FLT);
    float* bc1s = smf + FI_BC1;
    float* Wc2s = smf + FI_WC2;
    float* be2s = smf + FI_BE2;
    float* rc_s = smf + FI_RC;                         // [32][4]
    float* cwp  = smf + FI_CW;                         // [32]
    uint32_t* ebo_s = (uint32_t*)(smf + FI_EBO);       // [32]
    ull* F2u = (ull*)(smf + FI_F2);                    // [32][6]

    int tid = threadIdx.x;
    int w = tid >> 5, lane = tid & 31;
    const unsigned FULL = 0xffffffffu;
    float bc2v = bc2[0];
    uint32_t shm_base = smem_u32(smc) + OFF_SHM;

    // ---- weight preamble (once per block) ----
    for (int idx = tid; idx < 272 * 16; idx += 256) {
        int k2 = idx >> 4, n = idx & 15;
        float lo = (2 * k2     < HID) ? We2[(2 * k2)     * 16 + n] : 0.f;
        float hi = (2 * k2 + 1 < HID) ? We2[(2 * k2 + 1) * 16 + n] : 0.f;
        We2p[idx] = bf16x2_pack(lo, hi);
    }
    for (int idx = tid; idx < 2 * EPAD; idx += 256) {
        int c = idx >> 1, t = idx & 1;
        ulonglong2 v; v.x = 0ull; v.y = 0ull;
        if (c < HID) {
            v.x = pack2(We1[(size_t)(256 + 4 * t + 0) * HID + c], We1[(size_t)(256 + 4 * t + 1) * HID + c]);
            v.y = pack2(We1[(size_t)(256 + 4 * t + 2) * HID + c], We1[(size_t)(256 + 4 * t + 3) * HID + c]);
        }
        W9A[idx] = v;
    }
    for (int c = tid; c < EPAD; c += 256)
        W9Bf[c] = (c < HID) ? We1[(size_t)264 * HID + c] : 0.f;
    for (int idx = tid; idx < 16 * 64; idx += 256) Wc1s[idx] = Wc1[idx];
    if (tid < 64) { bc1s[tid] = bc1[tid]; Wc2s[tid] = Wc2[tid]; }
    if (tid >= 64 && tid < 80) be2s[tid - 64] = be2[tid - 64];
    __syncthreads();

#pragma unroll 1
    for (int nn = 0; nn < 4; nn++) {
        int node = blockIdx.x * 4 + nn;
        int b = node >> 12, i = node & (NNODES - 1);
        const float* cb = coors + (size_t)b * NNODES * 3;
        size_t aoff = (size_t)node * EPAD;

        // ---- setup (tid<32): knn, rel coords, fourier pairs ----
        if (tid < 32) {
            int e = tid;
            int j = g_knn[(size_t)node * KNN + e];
            ebo_s[e] = (uint32_t)(b * NNODES + j);
            float dx = cb[3 * i + 0] - cb[3 * j + 0];
            float dy = cb[3 * i + 1] - cb[3 * j + 1];
            float dz = cb[3 * i + 2] - cb[3 * j + 2];
            float d = dist2_f(dx, dy, dz);
            rc_s[e * 4 + 0] = dx; rc_s[e * 4 + 1] = dy; rc_s[e * 4 + 2] = dz; rc_s[e * 4 + 3] = 0.f;
            float s0, c0, s1, c1, s2, c2, s3, c3;
            sincosf(d,          &s0, &c0);
            sincosf(d * 0.5f,   &s1, &c1);
            sincosf(d * 0.25f,  &s2, &c2);
            sincosf(d * 0.125f, &s3, &c3);
            F2u[e * 6 + 0] = pack2(s0, s1);
            F2u[e * 6 + 1] = pack2(s2, s3);
            F2u[e * 6 + 2] = pack2(c0, c1);
            F2u[e * 6 + 3] = pack2(c2, c3);
            F2u[e * 6 + 4] = pack2(d, 0.f);
        }
        __syncthreads();

        int e0 = w * 4;
        uint32_t brow0 = ebo_s[e0 + 0], brow1 = ebo_s[e0 + 1];
        uint32_t brow2 = ebo_s[e0 + 2], brow3 = ebo_s[e0 + 3];

        float dacc[16];   // [mt*8 + nt*4 + r]
#pragma unroll
        for (int p = 0; p < 16; p++) dacc[p] = 0.f;

#pragma unroll 1
        for (int chunk = 0; chunk < 5; chunk++) {
            int nch = (chunk < 4) ? 128 : 32;
            int cbase = chunk * 128;

            // ---- P1: produce sh (bf16) for this warp's 4 edges ----
            {
                ull fpa[4][4]; float dd[4];
#pragma unroll
                for (int q = 0; q < 4; q++) {
#pragma unroll
                    for (int t = 0; t < 4; t++) fpa[q][t] = F2u[(e0 + q) * 6 + t];
                    dd[q] = ((const float*)&F2u[(e0 + q) * 6 + 4])[0];
                }
                int niter = nch >> 5;
#pragma unroll
                for (int it = 0; it < 4; it++) {
                    if (it >= niter) break;
                    int cl = it * 32 + lane;
                    int c = cbase + cl;
                    float av = g_A[aoff + c];
                    float bv[4];
                    bv[0] = g_B[(size_t)brow0 * EPAD + c];
                    bv[1] = g_B[(size_t)brow1 * EPAD + c];
                    bv[2] = g_B[(size_t)brow2 * EPAD + c];
                    bv[3] = g_B[(size_t)brow3 * EPAD + c];
                    ulonglong2 w9a0 = W9A[c * 2 + 0];
                    ulonglong2 w9a1 = W9A[c * 2 + 1];
                    float      w9b  = W9Bf[c];
#pragma unroll
                    for (int q = 0; q < 4; q++) {
                        ull ha = pack2(fmaf(dd[q], w9b, av + bv[q]), 0.f);
                        ull hb = 0ull;
                        ffma2(ha, fpa[q][0], w9a0.x);
                        ffma2(hb, fpa[q][1], w9a0.y);
                        ffma2(ha, fpa[q][2], w9a1.x);
                        ffma2(hb, fpa[q][3], w9a1.y);
                        float2 hv = unpack2(fadd2(ha, hb));
                        SHM16[(e0 + q) * 136 + cl] = __float2bfloat16(silu_f(hv.x + hv.y));
                    }
                }
            }
            __syncthreads();

            // ---- P2: tensor-core GEMM slice (k16-step = w) ----
            {
                int nk16 = nch >> 4;   // 8 or 2
                if (w < nk16) {
                    int k0 = w * 16;
                    int row = lane & 15, kh = (lane >> 4) * 8;
                    uint32_t addr0 = shm_base + (uint32_t)(row * 272 + (k0 + kh) * 2);
                    uint32_t addr1 = addr0 + 16u * 272u;
                    uint32_t a0[4], a1[4];
                    asm volatile("ldmatrix.sync.aligned.m8n8.x4.shared.b16 {%0,%1,%2,%3}, [%4];"
                                 : "=r"(a0[0]), "=r"(a0[1]), "=r"(a0[2]), "=r"(a0[3]) : "r"(addr0));
                    asm volatile("ldmatrix.sync.aligned.m8n8.x4.shared.b16 {%0,%1,%2,%3}, [%4];"
                                 : "=r"(a1[0]), "=r"(a1[1]), "=r"(a1[2]), "=r"(a1[3]) : "r"(addr1));
                    int g = lane >> 2, tg = lane & 3;
                    int k2b = chunk * 64 + w * 8;
                    uint32_t b00 = We2p[(k2b + tg) * 16 + g];
                    uint32_t b01 = We2p[(k2b + tg + 4) * 16 + g];
                    uint32_t b10 = We2p[(k2b + tg) * 16 + 8 + g];
                    uint32_t b11 = We2p[(k2b + tg + 4) * 16 + 8 + g];
                    asm volatile("mma.sync.aligned.m16n8k16.row.col.f32.bf16.bf16.f32 "
                                 "{%0,%1,%2,%3}, {%4,%5,%6,%7}, {%8,%9}, {%0,%1,%2,%3};"
                                 : "+f"(dacc[0]), "+f"(dacc[1]), "+f"(dacc[2]), "+f"(dacc[3])
                                 : "r"(a0[0]), "r"(a0[1]), "r"(a0[2]), "r"(a0[3]), "r"(b00), "r"(b01));
                    asm volatile("mma.sync.aligned.m16n8k16.row.col.f32.bf16.bf16.f32 "
                                 "{%0,%1,%2,%3}, {%4,%5,%6,%7}, {%8,%9}, {%0,%1,%2,%3};"
                                 : "+f"(dacc[4]), "+f"(dacc[5]), "+f"(dacc[6]), "+f"(dacc[7])
                                 : "r"(a0[0]), "r"(a0[1]), "r"(a0[2]), "r"(a0[3]), "r"(b10), "r"(b11));
                    asm volatile("mma.sync.aligned.m16n8k16.row.col.f32.bf16.bf16.f32 "
                                 "{%0,%1,%2,%3}, {%4,%5,%6,%7}, {%8,%9}, {%0,%1,%2,%3};"
                                 : "+f"(dacc[8]), "+f"(dacc[9]), "+f"(dacc[10]), "+f"(dacc[11])
                                 : "r"(a1[0]), "r"(a1[1]), "r"(a1[2]), "r"(a1[3]), "r"(b00), "r"(b01));
                    asm volatile("mma.sync.aligned.m16n8k16.row.col.f32.bf16.bf16.f32 "
                                 "{%0,%1,%2,%3}, {%4,%5,%6,%7}, {%8,%9}, {%0,%1,%2,%3};"
                                 : "+f"(dacc[12]), "+f"(dacc[13]), "+f"(dacc[14]), "+f"(dacc[15])
                                 : "r"(a1[0]), "r"(a1[1]), "r"(a1[2]), "r"(a1[3]), "r"(b10), "r"(b11));
                }
            }
            __syncthreads();   // SHM consumed; next P1 may overwrite
        }

        // ---- tree reduction of dacc across 8 warps (overlay on SHM) ----
#pragma unroll 1
        for (int step = 0; step < 3; step++) {
            int half = 4 >> step;              // 4, 2, 1
            if (w >= half && w < 2 * half) {
#pragma unroll
                for (int r4 = 0; r4 < 4; r4++)
                    *(float4*)(SHRf + (w - half) * 512 + lane * 16 + r4 * 4) =
                        make_float4(dacc[r4 * 4 + 0], dacc[r4 * 4 + 1],
                                    dacc[r4 * 4 + 2], dacc[r4 * 4 + 3]);
            }
            __syncthreads();
            if (w < half) {
#pragma unroll
                for (int r4 = 0; r4 < 4; r4++) {
                    float4 v = *(const float4*)(SHRf + w * 512 + lane * 16 + r4 * 4);
                    dacc[r4 * 4 + 0] += v.x; dacc[r4 * 4 + 1] += v.y;
                    dacc[r4 * 4 + 2] += v.z; dacc[r4 * 4 + 3] += v.w;
                }
            }
            __syncthreads();
        }
        if (w == 0) {
            int g = lane >> 2, tg = lane & 3;
#pragma unroll
            for (int mt = 0; mt < 2; mt++)
#pragma unroll
                for (int nt = 0; nt < 2; nt++) {
                    int e = mt * 16 + g, k = nt * 8 + tg * 2;
                    const float* dp = &dacc[mt * 8 + nt * 4];
                    msp[e * 16 + k + 0]       = silu_f(dp[0] + be2s[k + 0]);
                    msp[e * 16 + k + 1]       = silu_f(dp[1] + be2s[k + 1]);
                    msp[(e + 8) * 16 + k + 0] = silu_f(dp[2] + be2s[k + 0]);
                    msp[(e + 8) * 16 + k + 1] = silu_f(dp[3] + be2s[k + 1]);
                }
        }
        __syncthreads();

        // ---- coors MLP: 8 threads per edge (ms hoisted to registers) ----
        {
            int e = tid >> 3, li = tid & 7;
            float mloc[16];
#pragma unroll
            for (int r4 = 0; r4 < 4; r4++) {
                float4 v = *(const float4*)(msp + e * 16 + r4 * 4);
                mloc[r4 * 4 + 0] = v.x; mloc[r4 * 4 + 1] = v.y;
                mloc[r4 * 4 + 2] = v.z; mloc[r4 * 4 + 3] = v.w;
            }
            float wpart = 0.f;
#pragma unroll
            for (int q = 0; q < 8; q++) {
                int l = li * 8 + q;
                float u = bc1s[l];
#pragma unroll
                for (int k = 0; k < 16; k++)
                    u = fmaf(mloc[k], Wc1s[k * 64 + l], u);
                wpart = fmaf(silu_f(u), Wc2s[l], wpart);
            }
            wpart += __shfl_xor_sync(FULL, wpart, 1);
            wpart += __shfl_xor_sync(FULL, wpart, 2);
            wpart += __shfl_xor_sync(FULL, wpart, 4);
            if (li == 0) cwp[e] = wpart + bc2v;
        }
        __syncthreads();

        // ---- m_i (threads 0-15) and coors_out (warp 1) ----
        if (tid < 16) {
            float s = 0.f;
#pragma unroll 8
            for (int e2 = 0; e2 < 32; e2++) s += msp[e2 * 16 + tid];
            g_XC[(size_t)node * 144 + 128 + tid] = s;
        }
        if (w == 1) {
            int e2 = lane;
            float wv = cwp[e2];
            float px = wv * rc_s[e2 * 4 + 0];
            float py = wv * rc_s[e2 * 4 + 1];
            float pz = wv * rc_s[e2 * 4 + 2];
#pragma unroll
            for (int off = 16; off > 0; off >>= 1) {
                px += __shfl_down_sync(FULL, px, off);
                py += __shfl_down_sync(FULL, py, off);
                pz += __shfl_down_sync(FULL, pz, off);
            }
            if (e2 == 0) {
                float* co = coors_out + (size_t)node * 3;
                co[0] = cb[3 * i + 0] + px;
                co[1] = cb[3 * i + 1] + py;
                co[2] = cb[3 * i + 2] + pz;
            }
        }
        __syncthreads();
    }
}

// ---------------------------------------------------------------------------
extern "C" void kernel_launch(void* const* d_in, const int* in_sizes, int n_in,
                              void* d_out, int out_size) {
    const float* feats = (const float*)d_in[0];
    const float* coors = (const float*)d_in[1];
    const float* We1   = (const float*)d_in[2];
    const float* be1   = (const float*)d_in[3];
    const float* We2   = (const float*)d_in[4];
    const float* be2   = (const float*)d_in[5];
    const float* Wc1   = (const float*)d_in[6];
    const float* bc1   = (const float*)d_in[7];
    const float* Wc2   = (const float*)d_in[8];
    const float* bc2   = (const float*)d_in[9];
    const float* Wn1   = (const float*)d_in[10];
    const float* bn1   = (const float*)d_in[11];
    const float* Wn2   = (const float*)d_in[12];
    const float* bn2   = (const float*)d_in[13];
    float* out = (float*)d_out;
    float* node_out  = out;
    float* coors_out = out + NODE_OUT_ELEMS;

    float *pA, *pB, *pXC, *pH1;
    cudaGetSymbolAddress((void**)&pA, g_A);
    cudaGetSymbolAddress((void**)&pB, g_B);
    cudaGetSymbolAddress((void**)&pXC, g_XC);
    cudaGetSymbolAddress((void**)&pH1, g_H1);

    cudaFuncSetAttribute(edge_kernel, cudaFuncAttributeMaxDynamicSharedMemorySize, EK_SMEM_BYTES);

    // 1) KNN
    knn_kernel<<<NODES / 8, 256>>>(coors);

    // 2) A = feats @ We1[0:128,:] + be1 ; B = feats @ We1[128:256,:]  (pad->544)
    gemm_kernel<<<dim3(9, NODES / 64), 256>>>(feats, DIMF, We1, HID, be1, nullptr, 0,
                                              pA, EPAD, HID, EPAD, DIMF, 0);
    gemm_kernel<<<dim3(9, NODES / 64), 256>>>(feats, DIMF, We1 + 128 * HID, HID, nullptr, nullptr, 0,
                                              pB, EPAD, HID, EPAD, DIMF, 0);

    // 3) edges: m_ij -> m_i (XC[:,128:144]), coors_out
    edge_kernel<<<NODES / 4, 256, EK_SMEM_BYTES>>>(coors, We1, We2, be2,
                                                   Wc1, bc1, Wc2, bc2, coors_out);

    // 4) XC[:, 0:128] = feats
    copy_feats_kernel<<<(NODES * DIMF) / 256, 256>>>(feats);

    // 5) node MLP
    gemm_kernel<<<dim3(4, NODES / 64), 256>>>(pXC, 144, Wn1, 256, bn1, nullptr, 0,
                                              pH1, 256, 256, 256, 144, 1);
    gemm_kernel<<<dim3(2, NODES / 64), 256>>>(pH1, 256, Wn2, DIMF, bn2, feats, DIMF,
                                              node_out, DIMF, DIMF, DIMF, 256, 0);
}

// round 14
// speedup vs baseline: 1.3719x; 1.0497x over previous
#include <cuda_runtime.h>
#include <cuda_bf16.h>
#include <math.h>
#include <stdint.h>

#define BB 2
#define NNODES 4096
#define DIMF 128
#define KNN 32
#define HID 530
#define EPAD 544                    // padded hidden (17*32)
#define NODES (BB*NNODES)           // 8192
#define NODE_OUT_ELEMS (NODES*DIMF)

typedef unsigned long long ull;

// ---------------- scratch (static device arrays; no allocation) -------------
__device__ float g_A[NODES * EPAD];    // feats@We1[0:128]+be1 (pad cols zero)
__device__ float g_B[NODES * EPAD];    // feats@We1[128:256]   (pad cols zero)
__device__ float g_XC[NODES * 144];    // [feats | m_i]
__device__ float g_H1[NODES * 256];    // node hidden
__device__ int   g_knn[NODES * KNN];

// ---------------- f32x2 helpers ---------------------------------------------
__device__ __forceinline__ ull pack2(float lo, float hi) {
    ull u; asm("mov.b64 %0, {%1, %2};" : "=l"(u) : "f"(lo), "f"(hi)); return u;
}
__device__ __forceinline__ float2 unpack2(ull u) {
    float2 v; asm("mov.b64 {%0, %1}, %2;" : "=f"(v.x), "=f"(v.y) : "l"(u)); return v;
}
__device__ __forceinline__ void ffma2(ull& d, ull a, ull b) {
    asm("fma.rn.f32x2 %0, %1, %2, %0;" : "+l"(d) : "l"(a), "l"(b));
}
__device__ __forceinline__ ull fadd2(ull a, ull b) {
    ull d; asm("add.rn.f32x2 %0, %1, %2;" : "=l"(d) : "l"(a), "l"(b)); return d;
}

__device__ __forceinline__ float silu_f(float x) {
    float e = __expf(-x);
    return __fdividef(x, 1.0f + e);
}

__device__ __forceinline__ float dist2_f(float dx, float dy, float dz) {
    return __fadd_rn(__fadd_rn(__fmul_rn(dx, dx), __fmul_rn(dy, dy)), __fmul_rn(dz, dz));
}

__device__ __forceinline__ uint32_t smem_u32(const void* p) {
    uint32_t a;
    asm("{ .reg .u64 t; cvta.to.shared.u64 t, %1; cvt.u32.u64 %0, t; }" : "=r"(a) : "l"(p));
    return a;
}

__device__ __forceinline__ uint32_t bf16x2_pack(float lo, float hi) {
    uint32_t r;
    asm("cvt.rn.bf16x2.f32 %0, %1, %2;" : "=r"(r) : "f"(hi), "f"(lo));
    return r;
}

// ---------------------------------------------------------------------------
// KNN: one warp per (b,i). Unsorted top-32 set via warp REDUX threshold.
// ---------------------------------------------------------------------------
__global__ __launch_bounds__(256) void knn_kernel(const float* __restrict__ coors) {
    const unsigned FULL = 0xffffffffu;
    int w    = blockIdx.x * 8 + (threadIdx.x >> 5);
    int lane = threadIdx.x & 31;
    int b = w >> 12;
    int i = w & (NNODES - 1);
    const float* cb = coors + (size_t)b * NNODES * 3;
    float qx = cb[3 * i + 0], qy = cb[3 * i + 1], qz = cb[3 * i + 2];

    float dx = qx - cb[3 * lane + 0];
    float dy = qy - cb[3 * lane + 1];
    float dz = qz - cb[3 * lane + 2];
    unsigned bu = __float_as_uint(dist2_f(dx, dy, dz));
    int bj = lane;
    unsigned curmax = __reduce_max_sync(FULL, bu);

    for (int j0 = 32; j0 < NNODES; j0 += 32) {
        int j = j0 + lane;
        float ex = qx - cb[3 * j + 0];
        float ey = qy - cb[3 * j + 1];
        float ez = qz - cb[3 * j + 2];
        unsigned du = __float_as_uint(dist2_f(ex, ey, ez));
        unsigned mask = __ballot_sync(FULL, du < curmax);
        while (mask) {
            int src = __ffs(mask) - 1;
            mask &= mask - 1;
            unsigned dc = __shfl_sync(FULL, du, src);
            if (dc < curmax) {
                unsigned mm = __ballot_sync(FULL, bu == curmax);
                int ml = __ffs(mm) - 1;
                if (lane == ml) { bu = dc; bj = j0 + src; }
                curmax = __reduce_max_sync(FULL, bu);
            }
        }
    }
    g_knn[(size_t)w * KNN + lane] = bj;
}

// ---------------------------------------------------------------------------
// Tiled fp32 GEMM (FFMA2): C[.. x Npad] = act(X @ W + b) (+resid); pads -> 0
// ---------------------------------------------------------------------------
__global__ __launch_bounds__(256) void gemm_kernel(
    const float* __restrict__ X, int ldx,
    const float* __restrict__ W, int ldw,
    const float* __restrict__ bias,
    const float* __restrict__ resid, int ldr,
    float* __restrict__ C, int ldc,
    int Nw, int Npad, int K, int act)
{
    __shared__ float Xs[16][68];
    __shared__ float Ws[16][68];
    int tid = threadIdx.x;
    int tx = tid & 15, ty = tid >> 4;
    int m0 = blockIdx.y * 64, n0 = blockIdx.x * 64;

    int lm  = tid >> 2;
    int lk  = (tid & 3) * 4;
    int wn  = tid & 63;
    int wkb = (tid >> 6) * 4;

    ull acc2[4][2];
#pragma unroll
    for (int a = 0; a < 4; a++) { acc2[a][0] = 0ull; acc2[a][1] = 0ull; }

    for (int kt = 0; kt < K; kt += 16) {
        float4 xv = *reinterpret_cast<const float4*>(X + (size_t)(m0 + lm) * ldx + kt + lk);
        Xs[lk + 0][lm] = xv.x;
        Xs[lk + 1][lm] = xv.y;
        Xs[lk + 2][lm] = xv.z;
        Xs[lk + 3][lm] = xv.w;
#pragma unroll
        for (int q = 0; q < 4; q++) {
            int k = wkb + q;
            float v = (n0 + wn < Nw) ? W[(size_t)(kt + k) * ldw + n0 + wn] : 0.f;
            Ws[k][wn] = v;
        }
        __syncthreads();
#pragma unroll
        for (int k = 0; k < 16; k++) {
            float4 a4 = *reinterpret_cast<const float4*>(&Xs[k][ty * 4]);
            float4 b4 = *reinterpret_cast<const float4*>(&Ws[k][tx * 4]);
            ull b01 = pack2(b4.x, b4.y);
            ull b23 = pack2(b4.z, b4.w);
            float av[4] = {a4.x, a4.y, a4.z, a4.w};
#pragma unroll
            for (int mi = 0; mi < 4; mi++) {
                ull aa = pack2(av[mi], av[mi]);
                ffma2(acc2[mi][0], aa, b01);
                ffma2(acc2[mi][1], aa, b23);
            }
        }
        __syncthreads();
    }

#pragma unroll
    for (int mi = 0; mi < 4; mi++) {
        int m = m0 + ty * 4 + mi;
        float2 lo = unpack2(acc2[mi][0]);
        float2 hi = unpack2(acc2[mi][1]);
        float accv[4] = {lo.x, lo.y, hi.x, hi.y};
#pragma unroll
        for (int ni = 0; ni < 4; ni++) {
            int n = n0 + tx * 4 + ni;
            if (n < Npad) {
                float v = accv[ni];
                if (n < Nw) {
                    if (bias) v += bias[n];
                    if (act) v = silu_f(v);
                    if (resid) v += resid[(size_t)m * ldr + n];
                } else {
                    v = 0.f;
                }
                C[(size_t)m * ldc + n] = v;
            }
        }
    }
}

// ---------------------------------------------------------------------------
__global__ __launch_bounds__(256) void copy_feats_kernel(const float* __restrict__ feats) {
    int idx = blockIdx.x * 256 + threadIdx.x;  // over NODES*128
    int n = idx >> 7, c = idx & 127;
    g_XC[(size_t)n * 144 + c] = feats[idx];
}

// ---------------------------------------------------------------------------
// Edge kernel v6: P1 fp32 scalar (contiguous [t][c] fourier weights) +
// P2 tensor mma.sync bf16, double-buffered SHM (1 sync/chunk).
// 256 threads, 8 warps, 4 nodes/block, 3 blocks/SM.
// ---------------------------------------------------------------------------
#define OFF_WE2P  0                               // u32[272*16]        = 17408
#define OFF_FTA   17408                           // ulonglong2[2*544]  = 17408
#define OFF_W9B   34816                           // float[544]         = 2176
#define OFF_SHM   36992                           // 2 x bf16[32][136]  = 17408
#define SHM_BUF   8704
#define OFF_WC1   54400                           // float[16][64]      = 4096
#define OFF_MS    58496                           // float[32][16]      = 2048
#define OFF_FLT   60544
#define FI_BC1 0
#define FI_WC2 64
#define FI_BE2 128
#define FI_RC  144
#define FI_CW  272
#define FI_EBO 304
#define FI_F2  336                                // ull[32*6] (8B aligned)
#define FI_TOT (336 + 384)
#define EK_SMEM_BYTES (OFF_FLT + FI_TOT*4)        // 63424

__global__ __launch_bounds__(256, 3) void edge_kernel(
    const float* __restrict__ coors,
    const float* __restrict__ We1,
    const float* __restrict__ We2,
    const float* __restrict__ be2,
    const float* __restrict__ Wc1,
    const float* __restrict__ bc1,
    const float* __restrict__ Wc2,
    const float* __restrict__ bc2,
    float* __restrict__ coors_out)
{
    extern __shared__ char smc[];
    uint32_t* We2p = (uint32_t*)(smc + OFF_WE2P);      // [k2][16] bf16x2 pairs
    ulonglong2* FTA = (ulonglong2*)(smc + OFF_FTA);    // [t][c]: t=0 terms 0-3, t=1 terms 4-7
    float* W9Bf = (float*)(smc + OFF_W9B);
    __nv_bfloat16* SHM16 = (__nv_bfloat16*)(smc + OFF_SHM);   // double buffer
    float* SHRf = (float*)(smc + OFF_SHM + SHM_BUF);   // tree overlay on buffer 1
    float* Wc1s = (float*)(smc + OFF_WC1);
    float* msp  = (float*)(smc + OFF_MS);
    float* smf  = (float*)(smc + OFF_FLT);
    float* bc1s = smf + FI_BC1;
    float* Wc2s = smf + FI_WC2;
    float* be2s = smf + FI_BE2;
    float* rc_s = smf + FI_RC;                         // [32][4]
    float* cwp  = smf + FI_CW;                         // [32]
    uint32_t* ebo_s = (uint32_t*)(smf + FI_EBO);       // [32]
    ull* F2u = (ull*)(smf + FI_F2);                    // [32][6]

    int tid = threadIdx.x;
    int w = tid >> 5, lane = tid & 31;
    const unsigned FULL = 0xffffffffu;
    float bc2v = bc2[0];
    uint32_t shm_base0 = smem_u32(smc) + OFF_SHM;

    // ---- weight preamble (once per block) ----
    for (int idx = tid; idx < 272 * 16; idx += 256) {
        int k2 = idx >> 4, n = idx & 15;
        float lo = (2 * k2     < HID) ? We2[(2 * k2)     * 16 + n] : 0.f;
        float hi = (2 * k2 + 1 < HID) ? We2[(2 * k2 + 1) * 16 + n] : 0.f;
        We2p[idx] = bf16x2_pack(lo, hi);
    }
    for (int idx = tid; idx < 2 * EPAD; idx += 256) {
        int t = idx / EPAD, c = idx - t * EPAD;        // contiguous-in-c layout
        ulonglong2 v; v.x = 0ull; v.y = 0ull;
        if (c < HID) {
            v.x = pack2(We1[(size_t)(256 + 4 * t + 0) * HID + c], We1[(size_t)(256 + 4 * t + 1) * HID + c]);
            v.y = pack2(We1[(size_t)(256 + 4 * t + 2) * HID + c], We1[(size_t)(256 + 4 * t + 3) * HID + c]);
        }
        FTA[idx] = v;
    }
    for (int c = tid; c < EPAD; c += 256)
        W9Bf[c] = (c < HID) ? We1[(size_t)264 * HID + c] : 0.f;
    for (int idx = tid; idx < 16 * 64; idx += 256) Wc1s[idx] = Wc1[idx];
    if (tid < 64) { bc1s[tid] = bc1[tid]; Wc2s[tid] = Wc2[tid]; }
    if (tid >= 64 && tid < 80) be2s[tid - 64] = be2[tid - 64];
    __syncthreads();

#pragma unroll 1
    for (int nn = 0; nn < 4; nn++) {
        int node = blockIdx.x * 4 + nn;
        int b = node >> 12, i = node & (NNODES - 1);
        const float* cb = coors + (size_t)b * NNODES * 3;
        size_t aoff = (size_t)node * EPAD;

        // ---- setup (tid<32): knn, rel coords, fourier pairs ----
        if (tid < 32) {
            int e = tid;
            int j = g_knn[(size_t)node * KNN + e];
            ebo_s[e] = (uint32_t)(b * NNODES + j);
            float dx = cb[3 * i + 0] - cb[3 * j + 0];
            float dy = cb[3 * i + 1] - cb[3 * j + 1];
            float dz = cb[3 * i + 2] - cb[3 * j + 2];
            float d = dist2_f(dx, dy, dz);
            rc_s[e * 4 + 0] = dx; rc_s[e * 4 + 1] = dy; rc_s[e * 4 + 2] = dz; rc_s[e * 4 + 3] = 0.f;
            float s0, c0, s1, c1, s2, c2, s3, c3;
            sincosf(d,          &s0, &c0);
            sincosf(d * 0.5f,   &s1, &c1);
            sincosf(d * 0.25f,  &s2, &c2);
            sincosf(d * 0.125f, &s3, &c3);
            F2u[e * 6 + 0] = pack2(s0, s1);
            F2u[e * 6 + 1] = pack2(s2, s3);
            F2u[e * 6 + 2] = pack2(c0, c1);
            F2u[e * 6 + 3] = pack2(c2, c3);
            F2u[e * 6 + 4] = pack2(d, 0.f);
        }
        __syncthreads();

        int e0 = w * 4;
        uint32_t brow0 = ebo_s[e0 + 0], brow1 = ebo_s[e0 + 1];
        uint32_t brow2 = ebo_s[e0 + 2], brow3 = ebo_s[e0 + 3];

        float dacc[16];   // [mt*8 + nt*4 + r]
#pragma unroll
        for (int p = 0; p < 16; p++) dacc[p] = 0.f;

#pragma unroll 1
        for (int chunk = 0; chunk < 5; chunk++) {
            int nch = (chunk < 4) ? 128 : 32;
            int cbase = chunk * 128;
            int buf = chunk & 1;
            __nv_bfloat16* SHMb = SHM16 + buf * (SHM_BUF / 2);

            // ---- P1: produce sh (bf16) for this warp's 4 edges ----
            {
                ull fpa[4][4]; float dd[4];
#pragma unroll
                for (int q = 0; q < 4; q++) {
#pragma unroll
                    for (int t = 0; t < 4; t++) fpa[q][t] = F2u[(e0 + q) * 6 + t];
                    dd[q] = ((const float*)&F2u[(e0 + q) * 6 + 4])[0];
                }
                int niter = nch >> 5;
#pragma unroll
                for (int it = 0; it < 4; it++) {
                    if (it >= niter) break;
                    int cl = it * 32 + lane;
                    int c = cbase + cl;
                    float av = g_A[aoff + c];
                    float bv[4];
                    bv[0] = g_B[(size_t)brow0 * EPAD + c];
                    bv[1] = g_B[(size_t)brow1 * EPAD + c];
                    bv[2] = g_B[(size_t)brow2 * EPAD + c];
                    bv[3] = g_B[(size_t)brow3 * EPAD + c];
                    ulonglong2 w9a0 = FTA[c];          // terms 0-3, contiguous
                    ulonglong2 w9a1 = FTA[EPAD + c];   // terms 4-7, contiguous
                    float      w9b  = W9Bf[c];
#pragma unroll
                    for (int q = 0; q < 4; q++) {
                        ull ha = pack2(fmaf(dd[q], w9b, av + bv[q]), 0.f);
                        ull hb = 0ull;
                        ffma2(ha, fpa[q][0], w9a0.x);
                        ffma2(hb, fpa[q][1], w9a0.y);
                        ffma2(ha, fpa[q][2], w9a1.x);
                        ffma2(hb, fpa[q][3], w9a1.y);
                        float2 hv = unpack2(fadd2(ha, hb));
                        SHMb[(e0 + q) * 136 + cl] = __float2bfloat16(silu_f(hv.x + hv.y));
                    }
                }
            }
            __syncthreads();   // all P1(chunk) done (also orders prev P2 via program order)

            // ---- P2: tensor-core GEMM slice (k16-step = w) ----
            {
                int nk16 = nch >> 4;   // 8 or 2
                if (w < nk16) {
                    int k0 = w * 16;
                    int row = lane & 15, kh = (lane >> 4) * 8;
                    uint32_t addr0 = shm_base0 + (uint32_t)(buf * (SHM_BUF / 2) * 2)
                                   + (uint32_t)(row * 272 + (k0 + kh) * 2);
                    uint32_t addr1 = addr0 + 16u * 272u;
                    uint32_t a0[4], a1[4];
                    asm volatile("ldmatrix.sync.aligned.m8n8.x4.shared.b16 {%0,%1,%2,%3}, [%4];"
                                 : "=r"(a0[0]), "=r"(a0[1]), "=r"(a0[2]), "=r"(a0[3]) : "r"(addr0));
                    asm volatile("ldmatrix.sync.aligned.m8n8.x4.shared.b16 {%0,%1,%2,%3}, [%4];"
                                 : "=r"(a1[0]), "=r"(a1[1]), "=r"(a1[2]), "=r"(a1[3]) : "r"(addr1));
                    int g = lane >> 2, tg = lane & 3;
                    int k2b = chunk * 64 + w * 8;
                    uint32_t b00 = We2p[(k2b + tg) * 16 + g];
                    uint32_t b01 = We2p[(k2b + tg + 4) * 16 + g];
                    uint32_t b10 = We2p[(k2b + tg) * 16 + 8 + g];
                    uint32_t b11 = We2p[(k2b + tg + 4) * 16 + 8 + g];
                    asm volatile("mma.sync.aligned.m16n8k16.row.col.f32.bf16.bf16.f32 "
                                 "{%0,%1,%2,%3}, {%4,%5,%6,%7}, {%8,%9}, {%0,%1,%2,%3};"
                                 : "+f"(dacc[0]), "+f"(dacc[1]), "+f"(dacc[2]), "+f"(dacc[3])
                                 : "r"(a0[0]), "r"(a0[1]), "r"(a0[2]), "r"(a0[3]), "r"(b00), "r"(b01));
                    asm volatile("mma.sync.aligned.m16n8k16.row.col.f32.bf16.bf16.f32 "
                                 "{%0,%1,%2,%3}, {%4,%5,%6,%7}, {%8,%9}, {%0,%1,%2,%3};"
                                 : "+f"(dacc[4]), "+f"(dacc[5]), "+f"(dacc[6]), "+f"(dacc[7])
                                 : "r"(a0[0]), "r"(a0[1]), "r"(a0[2]), "r"(a0[3]), "r"(b10), "r"(b11));
                    asm volatile("mma.sync.aligned.m16n8k16.row.col.f32.bf16.bf16.f32 "
                                 "{%0,%1,%2,%3}, {%4,%5,%6,%7}, {%8,%9}, {%0,%1,%2,%3};"
                                 : "+f"(dacc[8]), "+f"(dacc[9]), "+f"(dacc[10]), "+f"(dacc[11])
                                 : "r"(a1[0]), "r"(a1[1]), "r"(a1[2]), "r"(a1[3]), "r"(b00), "r"(b01));
                    asm volatile("mma.sync.aligned.m16n8k16.row.col.f32.bf16.bf16.f32 "
                                 "{%0,%1,%2,%3}, {%4,%5,%6,%7}, {%8,%9}, {%0,%1,%2,%3};"
                                 : "+f"(dacc[12]), "+f"(dacc[13]), "+f"(dacc[14]), "+f"(dacc[15])
                                 : "r"(a1[0]), "r"(a1[1]), "r"(a1[2]), "r"(a1[3]), "r"(b10), "r"(b11));
                }
            }
            // no trailing sync: next P1 writes the OTHER buffer; the sync
            // before next P2 transitively orders this P2 for all warps.
        }

        // ---- tree reduction of dacc across 8 warps (overlay on buffer 1;
        //      final chunk's P2 read buffer 0, and buffer 1 is dead) ----
#pragma unroll 1
        for (int step = 0; step < 3; step++) {
            int half = 4 >> step;              // 4, 2, 1
            if (w >= half && w < 2 * half) {
#pragma unroll
                for (int r4 = 0; r4 < 4; r4++)
                    *(float4*)(SHRf + (w - half) * 512 + lane * 16 + r4 * 4) =
                        make_float4(dacc[r4 * 4 + 0], dacc[r4 * 4 + 1],
                                    dacc[r4 * 4 + 2], dacc[r4 * 4 + 3]);
            }
            __syncthreads();
            if (w < half) {
#pragma unroll
                for (int r4 = 0; r4 < 4; r4++) {
                    float4 v = *(const float4*)(SHRf + w * 512 + lane * 16 + r4 * 4);
                    dacc[r4 * 4 + 0] += v.x; dacc[r4 * 4 + 1] += v.y;
                    dacc[r4 * 4 + 2] += v.z; dacc[r4 * 4 + 3] += v.w;
                }
            }
            __syncthreads();
        }
        if (w == 0) {
            int g = lane >> 2, tg = lane & 3;
#pragma unroll
            for (int mt = 0; mt < 2; mt++)
#pragma unroll
                for (int nt = 0; nt < 2; nt++) {
                    int e = mt * 16 + g, k = nt * 8 + tg * 2;
                    const float* dp = &dacc[mt * 8 + nt * 4];
                    msp[e * 16 + k + 0]       = silu_f(dp[0] + be2s[k + 0]);
                    msp[e * 16 + k + 1]       = silu_f(dp[1] + be2s[k + 1]);
                    msp[(e + 8) * 16 + k + 0] = silu_f(dp[2] + be2s[k + 0]);
                    msp[(e + 8) * 16 + k + 1] = silu_f(dp[3] + be2s[k + 1]);
                }
        }
        __syncthreads();

        // ---- coors MLP: 8 threads per edge (ms hoisted to registers) ----
        {
            int e = tid >> 3, li = tid & 7;
            float mloc[16];
#pragma unroll
            for (int r4 = 0; r4 < 4; r4++) {
                float4 v = *(const float4*)(msp + e * 16 + r4 * 4);
                mloc[r4 * 4 + 0] = v.x; mloc[r4 * 4 + 1] = v.y;
                mloc[r4 * 4 + 2] = v.z; mloc[r4 * 4 + 3] = v.w;
            }
            float wpart = 0.f;
#pragma unroll
            for (int q = 0; q < 8; q++) {
                int l = li * 8 + q;
                float u = bc1s[l];
#pragma unroll
                for (int k = 0; k < 16; k++)
                    u = fmaf(mloc[k], Wc1s[k * 64 + l], u);
                wpart = fmaf(silu_f(u), Wc2s[l], wpart);
            }
            wpart += __shfl_xor_sync(FULL, wpart, 1);
            wpart += __shfl_xor_sync(FULL, wpart, 2);
            wpart += __shfl_xor_sync(FULL, wpart, 4);
            if (li == 0) cwp[e] = wpart + bc2v;
        }
        __syncthreads();

        // ---- m_i (threads 0-15) and coors_out (warp 1) ----
        if (tid < 16) {
            float s = 0.f;
#pragma unroll 8
            for (int e2 = 0; e2 < 32; e2++) s += msp[e2 * 16 + tid];
            g_XC[(size_t)node * 144 + 128 + tid] = s;
        }
        if (w == 1) {
            int e2 = lane;
            float wv = cwp[e2];
            float px = wv * rc_s[e2 * 4 + 0];
            float py = wv * rc_s[e2 * 4 + 1];
            float pz = wv * rc_s[e2 * 4 + 2];
#pragma unroll
            for (int off = 16; off > 0; off >>= 1) {
                px += __shfl_down_sync(FULL, px, off);
                py += __shfl_down_sync(FULL, py, off);
                pz += __shfl_down_sync(FULL, pz, off);
            }
            if (e2 == 0) {
                float* co = coors_out + (size_t)node * 3;
                co[0] = cb[3 * i + 0] + px;
                co[1] = cb[3 * i + 1] + py;
                co[2] = cb[3 * i + 2] + pz;
            }
        }
        __syncthreads();
    }
}

// ---------------------------------------------------------------------------
extern "C" void kernel_launch(void* const* d_in, const int* in_sizes, int n_in,
                              void* d_out, int out_size) {
    const float* feats = (const float*)d_in[0];
    const float* coors = (const float*)d_in[1];
    const float* We1   = (const float*)d_in[2];
    const float* be1   = (const float*)d_in[3];
    const float* We2   = (const float*)d_in[4];
    const float* be2   = (const float*)d_in[5];
    const float* Wc1   = (const float*)d_in[6];
    const float* bc1   = (const float*)d_in[7];
    const float* Wc2   = (const float*)d_in[8];
    const float* bc2   = (const float*)d_in[9];
    const float* Wn1   = (const float*)d_in[10];
    const float* bn1   = (const float*)d_in[11];
    const float* Wn2   = (const float*)d_in[12];
    const float* bn2   = (const float*)d_in[13];
    float* out = (float*)d_out;
    float* node_out  = out;
    float* coors_out = out + NODE_OUT_ELEMS;

    float *pA, *pB, *pXC, *pH1;
    cudaGetSymbolAddress((void**)&pA, g_A);
    cudaGetSymbolAddress((void**)&pB, g_B);
    cudaGetSymbolAddress((void**)&pXC, g_XC);
    cudaGetSymbolAddress((void**)&pH1, g_H1);

    cudaFuncSetAttribute(edge_kernel, cudaFuncAttributeMaxDynamicSharedMemorySize, EK_SMEM_BYTES);

    // 1) KNN
    knn_kernel<<<NODES / 8, 256>>>(coors);

    // 2) A = feats @ We1[0:128,:] + be1 ; B = feats @ We1[128:256,:]  (pad->544)
    gemm_kernel<<<dim3(9, NODES / 64), 256>>>(feats, DIMF, We1, HID, be1, nullptr, 0,
                                              pA, EPAD, HID, EPAD, DIMF, 0);
    gemm_kernel<<<dim3(9, NODES / 64), 256>>>(feats, DIMF, We1 + 128 * HID, HID, nullptr, nullptr, 0,
                                              pB, EPAD, HID, EPAD, DIMF, 0);

    // 3) edges: m_ij -> m_i (XC[:,128:144]), coors_out
    edge_kernel<<<NODES / 4, 256, EK_SMEM_BYTES>>>(coors, We1, We2, be2,
                                                   Wc1, bc1, Wc2, bc2, coors_out);

    // 4) XC[:, 0:128] = feats
    copy_feats_kernel<<<(NODES * DIMF) / 256, 256>>>(feats);

    // 5) node MLP
    gemm_kernel<<<dim3(4, NODES / 64), 256>>>(pXC, 144, Wn1, 256, bn1, nullptr, 0,
                                              pH1, 256, 256, 256, 144, 1);
    gemm_kernel<<<dim3(2, NODES / 64), 256>>>(pH1, 256, Wn2, DIMF, bn2, feats, DIMF,
                                              node_out, DIMF, DIMF, DIMF, 256, 0);
}

// round 15
// speedup vs baseline: 1.4235x; 1.0376x over previous
#include <cuda_runtime.h>
#include <cuda_bf16.h>
#include <math.h>
#include <stdint.h>

#define BB 2
#define NNODES 4096
#define DIMF 128
#define KNN 32
#define HID 530
#define EPAD 544                    // padded hidden (17*32)
#define NODES (BB*NNODES)           // 8192
#define NODE_OUT_ELEMS (NODES*DIMF)

typedef unsigned long long ull;

// ---------------- scratch (static device arrays; no allocation) -------------
__device__ float g_A[NODES * EPAD];    // feats@We1[0:128]+be1 (pad cols zero)
__device__ float g_B[NODES * EPAD];    // feats@We1[128:256]   (pad cols zero)
__device__ float g_XC[NODES * 144];    // [feats | m_i]
__device__ float g_H1[NODES * 256];    // node hidden
__device__ int   g_knn[NODES * KNN];

// ---------------- f32x2 helpers ---------------------------------------------
__device__ __forceinline__ ull pack2(float lo, float hi) {
    ull u; asm("mov.b64 %0, {%1, %2};" : "=l"(u) : "f"(lo), "f"(hi)); return u;
}
__device__ __forceinline__ float2 unpack2(ull u) {
    float2 v; asm("mov.b64 {%0, %1}, %2;" : "=f"(v.x), "=f"(v.y) : "l"(u)); return v;
}
__device__ __forceinline__ void ffma2(ull& d, ull a, ull b) {
    asm("fma.rn.f32x2 %0, %1, %2, %0;" : "+l"(d) : "l"(a), "l"(b));
}
__device__ __forceinline__ ull fadd2(ull a, ull b) {
    ull d; asm("add.rn.f32x2 %0, %1, %2;" : "=l"(d) : "l"(a), "l"(b)); return d;
}

__device__ __forceinline__ float silu_f(float x) {
    float e = __expf(-x);
    return __fdividef(x, 1.0f + e);
}

__device__ __forceinline__ float dist2_f(float dx, float dy, float dz) {
    return __fadd_rn(__fadd_rn(__fmul_rn(dx, dx), __fmul_rn(dy, dy)), __fmul_rn(dz, dz));
}

__device__ __forceinline__ uint32_t smem_u32(const void* p) {
    uint32_t a;
    asm("{ .reg .u64 t; cvta.to.shared.u64 t, %1; cvt.u32.u64 %0, t; }" : "=r"(a) : "l"(p));
    return a;
}

__device__ __forceinline__ uint32_t bf16x2_pack(float lo, float hi) {
    uint32_t r;
    asm("cvt.rn.bf16x2.f32 %0, %1, %2;" : "=r"(r) : "f"(hi), "f"(lo));
    return r;
}

// ---------------------------------------------------------------------------
// KNN: one warp per (b,i). Unsorted top-32 set via warp REDUX threshold.
// ---------------------------------------------------------------------------
__global__ __launch_bounds__(256) void knn_kernel(const float* __restrict__ coors) {
    const unsigned FULL = 0xffffffffu;
    int w    = blockIdx.x * 8 + (threadIdx.x >> 5);
    int lane = threadIdx.x & 31;
    int b = w >> 12;
    int i = w & (NNODES - 1);
    const float* cb = coors + (size_t)b * NNODES * 3;
    float qx = cb[3 * i + 0], qy = cb[3 * i + 1], qz = cb[3 * i + 2];

    float dx = qx - cb[3 * lane + 0];
    float dy = qy - cb[3 * lane + 1];
    float dz = qz - cb[3 * lane + 2];
    unsigned bu = __float_as_uint(dist2_f(dx, dy, dz));
    int bj = lane;
    unsigned curmax = __reduce_max_sync(FULL, bu);

    for (int j0 = 32; j0 < NNODES; j0 += 32) {
        int j = j0 + lane;
        float ex = qx - cb[3 * j + 0];
        float ey = qy - cb[3 * j + 1];
        float ez = qz - cb[3 * j + 2];
        unsigned du = __float_as_uint(dist2_f(ex, ey, ez));
        unsigned mask = __ballot_sync(FULL, du < curmax);
        while (mask) {
            int src = __ffs(mask) - 1;
            mask &= mask - 1;
            unsigned dc = __shfl_sync(FULL, du, src);
            if (dc < curmax) {
                unsigned mm = __ballot_sync(FULL, bu == curmax);
                int ml = __ffs(mm) - 1;
                if (lane == ml) { bu = dc; bj = j0 + src; }
                curmax = __reduce_max_sync(FULL, bu);
            }
        }
    }
    g_knn[(size_t)w * KNN + lane] = bj;
}

// ---------------------------------------------------------------------------
// Tiled fp32 GEMM (FFMA2): C[.. x Npad] = act(X @ W + b) (+resid); pads -> 0
// ---------------------------------------------------------------------------
__global__ __launch_bounds__(256) void gemm_kernel(
    const float* __restrict__ X, int ldx,
    const float* __restrict__ W, int ldw,
    const float* __restrict__ bias,
    const float* __restrict__ resid, int ldr,
    float* __restrict__ C, int ldc,
    int Nw, int Npad, int K, int act)
{
    __shared__ float Xs[16][68];
    __shared__ float Ws[16][68];
    int tid = threadIdx.x;
    int tx = tid & 15, ty = tid >> 4;
    int m0 = blockIdx.y * 64, n0 = blockIdx.x * 64;

    int lm  = tid >> 2;
    int lk  = (tid & 3) * 4;
    int wn  = tid & 63;
    int wkb = (tid >> 6) * 4;

    ull acc2[4][2];
#pragma unroll
    for (int a = 0; a < 4; a++) { acc2[a][0] = 0ull; acc2[a][1] = 0ull; }

    for (int kt = 0; kt < K; kt += 16) {
        float4 xv = *reinterpret_cast<const float4*>(X + (size_t)(m0 + lm) * ldx + kt + lk);
        Xs[lk + 0][lm] = xv.x;
        Xs[lk + 1][lm] = xv.y;
        Xs[lk + 2][lm] = xv.z;
        Xs[lk + 3][lm] = xv.w;
#pragma unroll
        for (int q = 0; q < 4; q++) {
            int k = wkb + q;
            float v = (n0 + wn < Nw) ? W[(size_t)(kt + k) * ldw + n0 + wn] : 0.f;
            Ws[k][wn] = v;
        }
        __syncthreads();
#pragma unroll
        for (int k = 0; k < 16; k++) {
            float4 a4 = *reinterpret_cast<const float4*>(&Xs[k][ty * 4]);
            float4 b4 = *reinterpret_cast<const float4*>(&Ws[k][tx * 4]);
            ull b01 = pack2(b4.x, b4.y);
            ull b23 = pack2(b4.z, b4.w);
            float av[4] = {a4.x, a4.y, a4.z, a4.w};
#pragma unroll
            for (int mi = 0; mi < 4; mi++) {
                ull aa = pack2(av[mi], av[mi]);
                ffma2(acc2[mi][0], aa, b01);
                ffma2(acc2[mi][1], aa, b23);
            }
        }
        __syncthreads();
    }

#pragma unroll
    for (int mi = 0; mi < 4; mi++) {
        int m = m0 + ty * 4 + mi;
        float2 lo = unpack2(acc2[mi][0]);
        float2 hi = unpack2(acc2[mi][1]);
        float accv[4] = {lo.x, lo.y, hi.x, hi.y};
#pragma unroll
        for (int ni = 0; ni < 4; ni++) {
            int n = n0 + tx * 4 + ni;
            if (n < Npad) {
                float v = accv[ni];
                if (n < Nw) {
                    if (bias) v += bias[n];
                    if (act) v = silu_f(v);
                    if (resid) v += resid[(size_t)m * ldr + n];
                } else {
                    v = 0.f;
                }
                C[(size_t)m * ldc + n] = v;
            }
        }
    }
}

// ---------------------------------------------------------------------------
__global__ __launch_bounds__(256) void copy_feats_kernel(const float* __restrict__ feats) {
    int idx = blockIdx.x * 256 + threadIdx.x;  // over NODES*128
    int n = idx >> 7, c = idx & 127;
    g_XC[(size_t)n * 144 + c] = feats[idx];
}

// ---------------------------------------------------------------------------
// Edge kernel v7: branch-free P1 (LDGs batchable), tensor P2, double-buffered
// SHM. 256 threads, 8 warps, 4 nodes/block, 3 blocks/SM.
// ---------------------------------------------------------------------------
#define OFF_WE2P  0                               // u32[272*16]        = 17408
#define OFF_FTA   17408                           // ulonglong2[2*544]  = 17408
#define OFF_W9B   34816                           // float[544]         = 2176
#define OFF_SHM   36992                           // 2 x bf16[32][136]  = 17408
#define SHM_BUF   8704
#define OFF_WC1   54400                           // float[16][64]      = 4096
#define OFF_MS    58496                           // float[32][16]      = 2048
#define OFF_FLT   60544
#define FI_BC1 0
#define FI_WC2 64
#define FI_BE2 128
#define FI_RC  144
#define FI_CW  272
#define FI_EBO 304
#define FI_F2  336                                // ull[32*6] (8B aligned)
#define FI_TOT (336 + 384)
#define EK_SMEM_BYTES (OFF_FLT + FI_TOT*4)        // 63424

// P1 body for one channel column cl (0..127 within chunk), writing to SHMb.
#define P1_BODY(SHMb, CBASE, CL) do { \
    int c = (CBASE) + (CL); \
    float av = g_A[aoff + c]; \
    float bv0 = g_B[(size_t)brow0 * EPAD + c]; \
    float bv1 = g_B[(size_t)brow1 * EPAD + c]; \
    float bv2 = g_B[(size_t)brow2 * EPAD + c]; \
    float bv3 = g_B[(size_t)brow3 * EPAD + c]; \
    ulonglong2 w9a0 = FTA[c]; \
    ulonglong2 w9a1 = FTA[EPAD + c]; \
    float w9b = W9Bf[c]; \
    float bvv[4] = {bv0, bv1, bv2, bv3}; \
    _Pragma("unroll") \
    for (int q = 0; q < 4; q++) { \
        ull ha = pack2(fmaf(dd[q], w9b, av + bvv[q]), 0.f); \
        ull hb = 0ull; \
        ffma2(ha, fpa[q][0], w9a0.x); \
        ffma2(hb, fpa[q][1], w9a0.y); \
        ffma2(ha, fpa[q][2], w9a1.x); \
        ffma2(hb, fpa[q][3], w9a1.y); \
        float2 hv = unpack2(fadd2(ha, hb)); \
        (SHMb)[(e0 + q) * 136 + (CL)] = __float2bfloat16(silu_f(hv.x + hv.y)); \
    } } while (0)

// P2 body: one k16-step at k2 base K2B reading from buffer byte-offset BUFB.
#define P2_BODY(BUFB, K2B) do { \
    int row = lane & 15, kh = (lane >> 4) * 8; \
    uint32_t addr0 = shm_base0 + (uint32_t)(BUFB) \
                   + (uint32_t)(row * 272 + ((K2B) * 2 - k2glob0 * 2) * 2 + kh * 2); \
    uint32_t addr1 = addr0 + 16u * 272u; \
    uint32_t a0[4], a1[4]; \
    asm volatile("ldmatrix.sync.aligned.m8n8.x4.shared.b16 {%0,%1,%2,%3}, [%4];" \
                 : "=r"(a0[0]), "=r"(a0[1]), "=r"(a0[2]), "=r"(a0[3]) : "r"(addr0)); \
    asm volatile("ldmatrix.sync.aligned.m8n8.x4.shared.b16 {%0,%1,%2,%3}, [%4];" \
                 : "=r"(a1[0]), "=r"(a1[1]), "=r"(a1[2]), "=r"(a1[3]) : "r"(addr1)); \
    int g = lane >> 2, tg = lane & 3; \
    uint32_t b00 = We2p[((K2B) + tg) * 16 + g]; \
    uint32_t b01 = We2p[((K2B) + tg + 4) * 16 + g]; \
    uint32_t b10 = We2p[((K2B) + tg) * 16 + 8 + g]; \
    uint32_t b11 = We2p[((K2B) + tg + 4) * 16 + 8 + g]; \
    asm volatile("mma.sync.aligned.m16n8k16.row.col.f32.bf16.bf16.f32 " \
                 "{%0,%1,%2,%3}, {%4,%5,%6,%7}, {%8,%9}, {%0,%1,%2,%3};" \
                 : "+f"(dacc[0]), "+f"(dacc[1]), "+f"(dacc[2]), "+f"(dacc[3]) \
                 : "r"(a0[0]), "r"(a0[1]), "r"(a0[2]), "r"(a0[3]), "r"(b00), "r"(b01)); \
    asm volatile("mma.sync.aligned.m16n8k16.row.col.f32.bf16.bf16.f32 " \
                 "{%0,%1,%2,%3}, {%4,%5,%6,%7}, {%8,%9}, {%0,%1,%2,%3};" \
                 : "+f"(dacc[4]), "+f"(dacc[5]), "+f"(dacc[6]), "+f"(dacc[7]) \
                 : "r"(a0[0]), "r"(a0[1]), "r"(a0[2]), "r"(a0[3]), "r"(b10), "r"(b11)); \
    asm volatile("mma.sync.aligned.m16n8k16.row.col.f32.bf16.bf16.f32 " \
                 "{%0,%1,%2,%3}, {%4,%5,%6,%7}, {%8,%9}, {%0,%1,%2,%3};" \
                 : "+f"(dacc[8]), "+f"(dacc[9]), "+f"(dacc[10]), "+f"(dacc[11]) \
                 : "r"(a1[0]), "r"(a1[1]), "r"(a1[2]), "r"(a1[3]), "r"(b00), "r"(b01)); \
    asm volatile("mma.sync.aligned.m16n8k16.row.col.f32.bf16.bf16.f32 " \
                 "{%0,%1,%2,%3}, {%4,%5,%6,%7}, {%8,%9}, {%0,%1,%2,%3};" \
                 : "+f"(dacc[12]), "+f"(dacc[13]), "+f"(dacc[14]), "+f"(dacc[15]) \
                 : "r"(a1[0]), "r"(a1[1]), "r"(a1[2]), "r"(a1[3]), "r"(b10), "r"(b11)); \
    } while (0)

__global__ __launch_bounds__(256, 3) void edge_kernel(
    const float* __restrict__ coors,
    const float* __restrict__ We1,
    const float* __restrict__ We2,
    const float* __restrict__ be2,
    const float* __restrict__ Wc1,
    const float* __restrict__ bc1,
    const float* __restrict__ Wc2,
    const float* __restrict__ bc2,
    float* __restrict__ coors_out)
{
    extern __shared__ char smc[];
    uint32_t* We2p = (uint32_t*)(smc + OFF_WE2P);      // [k2][16] bf16x2 pairs
    ulonglong2* FTA = (ulonglong2*)(smc + OFF_FTA);    // [t][c] contiguous
    float* W9Bf = (float*)(smc + OFF_W9B);
    __nv_bfloat16* SHM16 = (__nv_bfloat16*)(smc + OFF_SHM);   // double buffer
    float* SHRf = (float*)(smc + OFF_SHM + SHM_BUF);   // tree overlay on buffer 1
    float* Wc1s = (float*)(smc + OFF_WC1);
    float* msp  = (float*)(smc + OFF_MS);
    float* smf  = (float*)(smc + OFF_FLT);
    float* bc1s = smf + FI_BC1;
    float* Wc2s = smf + FI_WC2;
    float* be2s = smf + FI_BE2;
    float* rc_s = smf + FI_RC;                         // [32][4]
    float* cwp  = smf + FI_CW;                         // [32]
    uint32_t* ebo_s = (uint32_t*)(smf + FI_EBO);       // [32]
    ull* F2u = (ull*)(smf + FI_F2);                    // [32][6]

    int tid = threadIdx.x;
    int w = tid >> 5, lane = tid & 31;
    const unsigned FULL = 0xffffffffu;
    float bc2v = bc2[0];
    uint32_t shm_base0 = smem_u32(smc) + OFF_SHM;

    // ---- weight preamble (once per block) ----
    for (int idx = tid; idx < 272 * 16; idx += 256) {
        int k2 = idx >> 4, n = idx & 15;
        float lo = (2 * k2     < HID) ? We2[(2 * k2)     * 16 + n] : 0.f;
        float hi = (2 * k2 + 1 < HID) ? We2[(2 * k2 + 1) * 16 + n] : 0.f;
        We2p[idx] = bf16x2_pack(lo, hi);
    }
    for (int idx = tid; idx < 2 * EPAD; idx += 256) {
        int t = idx / EPAD, c = idx - t * EPAD;
        ulonglong2 v; v.x = 0ull; v.y = 0ull;
        if (c < HID) {
            v.x = pack2(We1[(size_t)(256 + 4 * t + 0) * HID + c], We1[(size_t)(256 + 4 * t + 1) * HID + c]);
            v.y = pack2(We1[(size_t)(256 + 4 * t + 2) * HID + c], We1[(size_t)(256 + 4 * t + 3) * HID + c]);
        }
        FTA[idx] = v;
    }
    for (int c = tid; c < EPAD; c += 256)
        W9Bf[c] = (c < HID) ? We1[(size_t)264 * HID + c] : 0.f;
    for (int idx = tid; idx < 16 * 64; idx += 256) Wc1s[idx] = Wc1[idx];
    if (tid < 64) { bc1s[tid] = bc1[tid]; Wc2s[tid] = Wc2[tid]; }
    if (tid >= 64 && tid < 80) be2s[tid - 64] = be2[tid - 64];
    __syncthreads();

#pragma unroll 1
    for (int nn = 0; nn < 4; nn++) {
        int node = blockIdx.x * 4 + nn;
        int b = node >> 12, i = node & (NNODES - 1);
        const float* cb = coors + (size_t)b * NNODES * 3;
        size_t aoff = (size_t)node * EPAD;

        // ---- setup (tid<32): knn, rel coords, fourier pairs ----
        if (tid < 32) {
            int e = tid;
            int j = g_knn[(size_t)node * KNN + e];
            ebo_s[e] = (uint32_t)(b * NNODES + j);
            float dx = cb[3 * i + 0] - cb[3 * j + 0];
            float dy = cb[3 * i + 1] - cb[3 * j + 1];
            float dz = cb[3 * i + 2] - cb[3 * j + 2];
            float d = dist2_f(dx, dy, dz);
            rc_s[e * 4 + 0] = dx; rc_s[e * 4 + 1] = dy; rc_s[e * 4 + 2] = dz; rc_s[e * 4 + 3] = 0.f;
            float s0, c0, s1, c1, s2, c2, s3, c3;
            sincosf(d,          &s0, &c0);
            sincosf(d * 0.5f,   &s1, &c1);
            sincosf(d * 0.25f,  &s2, &c2);
            sincosf(d * 0.125f, &s3, &c3);
            F2u[e * 6 + 0] = pack2(s0, s1);
            F2u[e * 6 + 1] = pack2(s2, s3);
            F2u[e * 6 + 2] = pack2(c0, c1);
            F2u[e * 6 + 3] = pack2(c2, c3);
            F2u[e * 6 + 4] = pack2(d, 0.f);
        }
        __syncthreads();

        int e0 = w * 4;
        uint32_t brow0 = ebo_s[e0 + 0], brow1 = ebo_s[e0 + 1];
        uint32_t brow2 = ebo_s[e0 + 2], brow3 = ebo_s[e0 + 3];

        // per-edge fourier registers for this warp (loaded once per node)
        ull fpa[4][4]; float dd[4];
#pragma unroll
        for (int q = 0; q < 4; q++) {
#pragma unroll
            for (int t = 0; t < 4; t++) fpa[q][t] = F2u[(e0 + q) * 6 + t];
            dd[q] = ((const float*)&F2u[(e0 + q) * 6 + 4])[0];
        }

        float dacc[16];
#pragma unroll
        for (int p = 0; p < 16; p++) dacc[p] = 0.f;
        const int k2glob0 = 0;   // used by P2_BODY addressing (relative)

        // ---- main chunks 0..3: branch-free P1 (batched LDGs) + full P2 ----
#pragma unroll 1
        for (int chunk = 0; chunk < 4; chunk++) {
            int cbase = chunk * 128;
            int buf = chunk & 1;
            __nv_bfloat16* SHMb = SHM16 + buf * (SHM_BUF / 2);

#pragma unroll
            for (int it = 0; it < 4; it++) {
                int cl = it * 32 + lane;
                P1_BODY(SHMb, cbase, cl);
            }
            __syncthreads();

            {
                int k2b = chunk * 64 + w * 8;
                int bufb = buf * SHM_BUF;
                // address within buffer: row*272 + (local k16 offset)
                int row = lane & 15, kh = (lane >> 4) * 8;
                uint32_t addr0 = shm_base0 + (uint32_t)bufb
                               + (uint32_t)(row * 272 + (w * 16 + kh) * 2);
                uint32_t addr1 = addr0 + 16u * 272u;
                uint32_t a0[4], a1[4];
                asm volatile("ldmatrix.sync.aligned.m8n8.x4.shared.b16 {%0,%1,%2,%3}, [%4];"
                             : "=r"(a0[0]), "=r"(a0[1]), "=r"(a0[2]), "=r"(a0[3]) : "r"(addr0));
                asm volatile("ldmatrix.sync.aligned.m8n8.x4.shared.b16 {%0,%1,%2,%3}, [%4];"
                             : "=r"(a1[0]), "=r"(a1[1]), "=r"(a1[2]), "=r"(a1[3]) : "r"(addr1));
                int g = lane >> 2, tg = lane & 3;
                uint32_t b00 = We2p[(k2b + tg) * 16 + g];
                uint32_t b01 = We2p[(k2b + tg + 4) * 16 + g];
                uint32_t b10 = We2p[(k2b + tg) * 16 + 8 + g];
                uint32_t b11 = We2p[(k2b + tg + 4) * 16 + 8 + g];
                asm volatile("mma.sync.aligned.m16n8k16.row.col.f32.bf16.bf16.f32 "
                             "{%0,%1,%2,%3}, {%4,%5,%6,%7}, {%8,%9}, {%0,%1,%2,%3};"
                             : "+f"(dacc[0]), "+f"(dacc[1]), "+f"(dacc[2]), "+f"(dacc[3])
                             : "r"(a0[0]), "r"(a0[1]), "r"(a0[2]), "r"(a0[3]), "r"(b00), "r"(b01));
                asm volatile("mma.sync.aligned.m16n8k16.row.col.f32.bf16.bf16.f32 "
                             "{%0,%1,%2,%3}, {%4,%5,%6,%7}, {%8,%9}, {%0,%1,%2,%3};"
                             : "+f"(dacc[4]), "+f"(dacc[5]), "+f"(dacc[6]), "+f"(dacc[7])
                             : "r"(a0[0]), "r"(a0[1]), "r"(a0[2]), "r"(a0[3]), "r"(b10), "r"(b11));
                asm volatile("mma.sync.aligned.m16n8k16.row.col.f32.bf16.bf16.f32 "
                             "{%0,%1,%2,%3}, {%4,%5,%6,%7}, {%8,%9}, {%0,%1,%2,%3};"
                             : "+f"(dacc[8]), "+f"(dacc[9]), "+f"(dacc[10]), "+f"(dacc[11])
                             : "r"(a1[0]), "r"(a1[1]), "r"(a1[2]), "r"(a1[3]), "r"(b00), "r"(b01));
                asm volatile("mma.sync.aligned.m16n8k16.row.col.f32.bf16.bf16.f32 "
                             "{%0,%1,%2,%3}, {%4,%5,%6,%7}, {%8,%9}, {%0,%1,%2,%3};"
                             : "+f"(dacc[12]), "+f"(dacc[13]), "+f"(dacc[14]), "+f"(dacc[15])
                             : "r"(a1[0]), "r"(a1[1]), "r"(a1[2]), "r"(a1[3]), "r"(b10), "r"(b11));
            }
            // no trailing sync: next P1 writes the OTHER buffer.
        }

        // ---- tail chunk (channels 512..543), buffer 0 ----
        {
            P1_BODY(SHM16, 512, lane);
        }
        __syncthreads();
        if (w < 2) {
            int k2b = 256 + w * 8;
            int row = lane & 15, kh = (lane >> 4) * 8;
            uint32_t addr0 = shm_base0 + (uint32_t)(row * 272 + (w * 16 + kh) * 2);
            uint32_t addr1 = addr0 + 16u * 272u;
            uint32_t a0[4], a1[4];
            asm volatile("ldmatrix.sync.aligned.m8n8.x4.shared.b16 {%0,%1,%2,%3}, [%4];"
                         : "=r"(a0[0]), "=r"(a0[1]), "=r"(a0[2]), "=r"(a0[3]) : "r"(addr0));
            asm volatile("ldmatrix.sync.aligned.m8n8.x4.shared.b16 {%0,%1,%2,%3}, [%4];"
                         : "=r"(a1[0]), "=r"(a1[1]), "=r"(a1[2]), "=r"(a1[3]) : "r"(addr1));
            int g = lane >> 2, tg = lane & 3;
            uint32_t b00 = We2p[(k2b + tg) * 16 + g];
            uint32_t b01 = We2p[(k2b + tg + 4) * 16 + g];
            uint32_t b10 = We2p[(k2b + tg) * 16 + 8 + g];
            uint32_t b11 = We2p[(k2b + tg + 4) * 16 + 8 + g];
            asm volatile("mma.sync.aligned.m16n8k16.row.col.f32.bf16.bf16.f32 "
                         "{%0,%1,%2,%3}, {%4,%5,%6,%7}, {%8,%9}, {%0,%1,%2,%3};"
                         : "+f"(dacc[0]), "+f"(dacc[1]), "+f"(dacc[2]), "+f"(dacc[3])
                         : "r"(a0[0]), "r"(a0[1]), "r"(a0[2]), "r"(a0[3]), "r"(b00), "r"(b01));
            asm volatile("mma.sync.aligned.m16n8k16.row.col.f32.bf16.bf16.f32 "
                         "{%0,%1,%2,%3}, {%4,%5,%6,%7}, {%8,%9}, {%0,%1,%2,%3};"
                         : "+f"(dacc[4]), "+f"(dacc[5]), "+f"(dacc[6]), "+f"(dacc[7])
                         : "r"(a0[0]), "r"(a0[1]), "r"(a0[2]), "r"(a0[3]), "r"(b10), "r"(b11));
            asm volatile("mma.sync.aligned.m16n8k16.row.col.f32.bf16.bf16.f32 "
                         "{%0,%1,%2,%3}, {%4,%5,%6,%7}, {%8,%9}, {%0,%1,%2,%3};"
                         : "+f"(dacc[8]), "+f"(dacc[9]), "+f"(dacc[10]), "+f"(dacc[11])
                         : "r"(a1[0]), "r"(a1[1]), "r"(a1[2]), "r"(a1[3]), "r"(b00), "r"(b01));
            asm volatile("mma.sync.aligned.m16n8k16.row.col.f32.bf16.bf16.f32 "
                         "{%0,%1,%2,%3}, {%4,%5,%6,%7}, {%8,%9}, {%0,%1,%2,%3};"
                         : "+f"(dacc[12]), "+f"(dacc[13]), "+f"(dacc[14]), "+f"(dacc[15])
                         : "r"(a1[0]), "r"(a1[1]), "r"(a1[2]), "r"(a1[3]), "r"(b10), "r"(b11));
        }

        // ---- tree reduction of dacc across 8 warps (overlay on buffer 1;
        //      tail P2 read buffer 0) ----
#pragma unroll 1
        for (int step = 0; step < 3; step++) {
            int half = 4 >> step;              // 4, 2, 1
            if (w >= half && w < 2 * half) {
#pragma unroll
                for (int r4 = 0; r4 < 4; r4++)
                    *(float4*)(SHRf + (w - half) * 512 + lane * 16 + r4 * 4) =
                        make_float4(dacc[r4 * 4 + 0], dacc[r4 * 4 + 1],
                                    dacc[r4 * 4 + 2], dacc[r4 * 4 + 3]);
            }
            __syncthreads();
            if (w < half) {
#pragma unroll
                for (int r4 = 0; r4 < 4; r4++) {
                    float4 v = *(const float4*)(SHRf + w * 512 + lane * 16 + r4 * 4);
                    dacc[r4 * 4 + 0] += v.x; dacc[r4 * 4 + 1] += v.y;
                    dacc[r4 * 4 + 2] += v.z; dacc[r4 * 4 + 3] += v.w;
                }
            }
            __syncthreads();
        }
        if (w == 0) {
            int g = lane >> 2, tg = lane & 3;
#pragma unroll
            for (int mt = 0; mt < 2; mt++)
#pragma unroll
                for (int nt = 0; nt < 2; nt++) {
                    int e = mt * 16 + g, k = nt * 8 + tg * 2;
                    const float* dp = &dacc[mt * 8 + nt * 4];
                    msp[e * 16 + k + 0]       = silu_f(dp[0] + be2s[k + 0]);
                    msp[e * 16 + k + 1]       = silu_f(dp[1] + be2s[k + 1]);
                    msp[(e + 8) * 16 + k + 0] = silu_f(dp[2] + be2s[k + 0]);
                    msp[(e + 8) * 16 + k + 1] = silu_f(dp[3] + be2s[k + 1]);
                }
        }
        __syncthreads();

        // ---- coors MLP: 8 threads per edge (ms hoisted to registers) ----
        {
            int e = tid >> 3, li = tid & 7;
            float mloc[16];
#pragma unroll
            for (int r4 = 0; r4 < 4; r4++) {
                float4 v = *(const float4*)(msp + e * 16 + r4 * 4);
                mloc[r4 * 4 + 0] = v.x; mloc[r4 * 4 + 1] = v.y;
                mloc[r4 * 4 + 2] = v.z; mloc[r4 * 4 + 3] = v.w;
            }
            float wpart = 0.f;
#pragma unroll
            for (int q = 0; q < 8; q++) {
                int l = li * 8 + q;
                float u = bc1s[l];
#pragma unroll
                for (int k = 0; k < 16; k++)
                    u = fmaf(mloc[k], Wc1s[k * 64 + l], u);
                wpart = fmaf(silu_f(u), Wc2s[l], wpart);
            }
            wpart += __shfl_xor_sync(FULL, wpart, 1);
            wpart += __shfl_xor_sync(FULL, wpart, 2);
            wpart += __shfl_xor_sync(FULL, wpart, 4);
            if (li == 0) cwp[e] = wpart + bc2v;
        }
        __syncthreads();

        // ---- m_i (threads 0-15) and coors_out (warp 1) ----
        if (tid < 16) {
            float s = 0.f;
#pragma unroll 8
            for (int e2 = 0; e2 < 32; e2++) s += msp[e2 * 16 + tid];
            g_XC[(size_t)node * 144 + 128 + tid] = s;
        }
        if (w == 1) {
            int e2 = lane;
            float wv = cwp[e2];
            float px = wv * rc_s[e2 * 4 + 0];
            float py = wv * rc_s[e2 * 4 + 1];
            float pz = wv * rc_s[e2 * 4 + 2];
#pragma unroll
            for (int off = 16; off > 0; off >>= 1) {
                px += __shfl_down_sync(FULL, px, off);
                py += __shfl_down_sync(FULL, py, off);
                pz += __shfl_down_sync(FULL, pz, off);
            }
            if (e2 == 0) {
                float* co = coors_out + (size_t)node * 3;
                co[0] = cb[3 * i + 0] + px;
                co[1] = cb[3 * i + 1] + py;
                co[2] = cb[3 * i + 2] + pz;
            }
        }
        __syncthreads();
    }
}

// ---------------------------------------------------------------------------
extern "C" void kernel_launch(void* const* d_in, const int* in_sizes, int n_in,
                              void* d_out, int out_size) {
    const float* feats = (const float*)d_in[0];
    const float* coors = (const float*)d_in[1];
    const float* We1   = (const float*)d_in[2];
    const float* be1   = (const float*)d_in[3];
    const float* We2   = (const float*)d_in[4];
    const float* be2   = (const float*)d_in[5];
    const float* Wc1   = (const float*)d_in[6];
    const float* bc1   = (const float*)d_in[7];
    const float* Wc2   = (const float*)d_in[8];
    const float* bc2   = (const float*)d_in[9];
    const float* Wn1   = (const float*)d_in[10];
    const float* bn1   = (const float*)d_in[11];
    const float* Wn2   = (const float*)d_in[12];
    const float* bn2   = (const float*)d_in[13];
    float* out = (float*)d_out;
    float* node_out  = out;
    float* coors_out = out + NODE_OUT_ELEMS;

    float *pA, *pB, *pXC, *pH1;
    cudaGetSymbolAddress((void**)&pA, g_A);
    cudaGetSymbolAddress((void**)&pB, g_B);
    cudaGetSymbolAddress((void**)&pXC, g_XC);
    cudaGetSymbolAddress((void**)&pH1, g_H1);

    cudaFuncSetAttribute(edge_kernel, cudaFuncAttributeMaxDynamicSharedMemorySize, EK_SMEM_BYTES);

    // 1) KNN
    knn_kernel<<<NODES / 8, 256>>>(coors);

    // 2) A = feats @ We1[0:128,:] + be1 ; B = feats @ We1[128:256,:]  (pad->544)
    gemm_kernel<<<dim3(9, NODES / 64), 256>>>(feats, DIMF, We1, HID, be1, nullptr, 0,
                                              pA, EPAD, HID, EPAD, DIMF, 0);
    gemm_kernel<<<dim3(9, NODES / 64), 256>>>(feats, DIMF, We1 + 128 * HID, HID, nullptr, nullptr, 0,
                                              pB, EPAD, HID, EPAD, DIMF, 0);

    // 3) edges: m_ij -> m_i (XC[:,128:144]), coors_out
    edge_kernel<<<NODES / 4, 256, EK_SMEM_BYTES>>>(coors, We1, We2, be2,
                                                   Wc1, bc1, Wc2, bc2, coors_out);

    // 4) XC[:, 0:128] = feats
    copy_feats_kernel<<<(NODES * DIMF) / 256, 256>>>(feats);

    // 5) node MLP
    gemm_kernel<<<dim3(4, NODES / 64), 256>>>(pXC, 144, Wn1, 256, bn1, nullptr, 0,
                                              pH1, 256, 256, 256, 144, 1);
    gemm_kernel<<<dim3(2, NODES / 64), 256>>>(pH1, 256, Wn2, DIMF, bn2, feats, DIMF,
                                              node_out, DIMF, DIMF, DIMF, 256, 0);
}

// round 16
// speedup vs baseline: 1.5577x; 1.0942x over previous
#include <cuda_runtime.h>
#include <cuda_bf16.h>
#include <math.h>
#include <stdint.h>

#define BB 2
#define NNODES 4096
#define DIMF 128
#define KNN 32
#define HID 530
#define EPAD 544                    // padded hidden (17*32)
#define NODES (BB*NNODES)           // 8192
#define NODE_OUT_ELEMS (NODES*DIMF)

typedef unsigned long long ull;

// ---------------- scratch (static device arrays; no allocation) -------------
__device__ float g_A[NODES * EPAD];    // feats@We1[0:128]+be1 (pad cols zero)
__device__ float g_B[NODES * EPAD];    // feats@We1[128:256]   (pad cols zero)
__device__ float g_XC[NODES * 144];    // [feats | m_i]
__device__ float g_H1[NODES * 256];    // node hidden
__device__ int   g_knn[NODES * KNN];

// ---------------- f32x2 helpers ---------------------------------------------
__device__ __forceinline__ ull pack2(float lo, float hi) {
    ull u; asm("mov.b64 %0, {%1, %2};" : "=l"(u) : "f"(lo), "f"(hi)); return u;
}
__device__ __forceinline__ float2 unpack2(ull u) {
    float2 v; asm("mov.b64 {%0, %1}, %2;" : "=f"(v.x), "=f"(v.y) : "l"(u)); return v;
}
__device__ __forceinline__ void ffma2(ull& d, ull a, ull b) {
    asm("fma.rn.f32x2 %0, %1, %2, %0;" : "+l"(d) : "l"(a), "l"(b));
}
__device__ __forceinline__ ull fadd2(ull a, ull b) {
    ull d; asm("add.rn.f32x2 %0, %1, %2;" : "=l"(d) : "l"(a), "l"(b)); return d;
}

__device__ __forceinline__ float silu_f(float x) {
    float e = __expf(-x);
    return __fdividef(x, 1.0f + e);
}

__device__ __forceinline__ float dist2_f(float dx, float dy, float dz) {
    return __fadd_rn(__fadd_rn(__fmul_rn(dx, dx), __fmul_rn(dy, dy)), __fmul_rn(dz, dz));
}

__device__ __forceinline__ uint32_t smem_u32(const void* p) {
    uint32_t a;
    asm("{ .reg .u64 t; cvta.to.shared.u64 t, %1; cvt.u32.u64 %0, t; }" : "=r"(a) : "l"(p));
    return a;
}

__device__ __forceinline__ uint32_t bf16x2_pack(float lo, float hi) {
    uint32_t r;
    asm("cvt.rn.bf16x2.f32 %0, %1, %2;" : "=r"(r) : "f"(hi), "f"(lo));
    return r;
}

// ---------------------------------------------------------------------------
// KNN: one warp per (b,i). Unsorted top-32 set via warp REDUX threshold.
// ---------------------------------------------------------------------------
__global__ __launch_bounds__(256) void knn_kernel(const float* __restrict__ coors) {
    const unsigned FULL = 0xffffffffu;
    int w    = blockIdx.x * 8 + (threadIdx.x >> 5);
    int lane = threadIdx.x & 31;
    int b = w >> 12;
    int i = w & (NNODES - 1);
    const float* cb = coors + (size_t)b * NNODES * 3;
    float qx = cb[3 * i + 0], qy = cb[3 * i + 1], qz = cb[3 * i + 2];

    float dx = qx - cb[3 * lane + 0];
    float dy = qy - cb[3 * lane + 1];
    float dz = qz - cb[3 * lane + 2];
    unsigned bu = __float_as_uint(dist2_f(dx, dy, dz));
    int bj = lane;
    unsigned curmax = __reduce_max_sync(FULL, bu);

    for (int j0 = 32; j0 < NNODES; j0 += 32) {
        int j = j0 + lane;
        float ex = qx - cb[3 * j + 0];
        float ey = qy - cb[3 * j + 1];
        float ez = qz - cb[3 * j + 2];
        unsigned du = __float_as_uint(dist2_f(ex, ey, ez));
        unsigned mask = __ballot_sync(FULL, du < curmax);
        while (mask) {
            int src = __ffs(mask) - 1;
            mask &= mask - 1;
            unsigned dc = __shfl_sync(FULL, du, src);
            if (dc < curmax) {
                unsigned mm = __ballot_sync(FULL, bu == curmax);
                int ml = __ffs(mm) - 1;
                if (lane == ml) { bu = dc; bj = j0 + src; }
                curmax = __reduce_max_sync(FULL, bu);
            }
        }
    }
    g_knn[(size_t)w * KNN + lane] = bj;
}

// ---------------------------------------------------------------------------
// Tensor-core bf16 GEMM: C[.. x Npad] = act(X @ W + b) (+resid); pads -> 0.
// 256 threads, BM=64, BN=64, BK=16; warp (wm,wn) owns m16 x n32.
// X,W converted fp32->bf16 on smem load; fp32 accumulate. K mult of 16.
// ---------------------------------------------------------------------------
__global__ __launch_bounds__(256) void gemm16_kernel(
    const float* __restrict__ X, int ldx,
    const float* __restrict__ W, int ldw,
    const float* __restrict__ bias,
    const float* __restrict__ resid, int ldr,
    float* __restrict__ C, int ldc,
    int Nw, int Npad, int K, int act)
{
    __shared__ uint32_t Xs[64 * 8];     // [m][k2] bf16 pairs, row = 8 u32 (32B)
    __shared__ uint32_t Ws[8 * 64];     // [k2][n] pairs (k, k+1) down column n
    int tid = threadIdx.x;
    int w = tid >> 5, lane = tid & 31;
    int wm = w >> 1, wn = w & 1;
    int m0 = blockIdx.y * 64, n0 = blockIdx.x * 64;

    float dacc[16];
#pragma unroll
    for (int p = 0; p < 16; p++) dacc[p] = 0.f;

    int xr = tid >> 2;              // X-load row 0..63
    int xp = (tid & 3) * 2;         // X-load pair base 0..6
    int wcol = tid & 63;            // W-load col
    int wk2  = (tid >> 6) * 2;      // W-load k2 base 0..6

    uint32_t xaddr = smem_u32(Xs);
    int g = lane >> 2, tg = lane & 3;

    for (int kt = 0; kt < K; kt += 16) {
        float4 xv = *(const float4*)(X + (size_t)(m0 + xr) * ldx + kt + xp * 2);
        Xs[xr * 8 + xp]     = bf16x2_pack(xv.x, xv.y);
        Xs[xr * 8 + xp + 1] = bf16x2_pack(xv.z, xv.w);
#pragma unroll
        for (int q = 0; q < 2; q++) {
            int k2 = wk2 + q;
            float lo = 0.f, hi = 0.f;
            if (n0 + wcol < Nw) {
                lo = W[(size_t)(kt + 2 * k2)     * ldw + n0 + wcol];
                hi = W[(size_t)(kt + 2 * k2 + 1) * ldw + n0 + wcol];
            }
            Ws[k2 * 64 + wcol] = bf16x2_pack(lo, hi);
        }
        __syncthreads();

        uint32_t a[4];
        uint32_t addr = xaddr + (uint32_t)((wm * 16 + (lane & 15)) * 32 + (lane >> 4) * 16);
        asm volatile("ldmatrix.sync.aligned.m8n8.x4.shared.b16 {%0,%1,%2,%3}, [%4];"
                     : "=r"(a[0]), "=r"(a[1]), "=r"(a[2]), "=r"(a[3]) : "r"(addr));
#pragma unroll
        for (int nf = 0; nf < 4; nf++) {
            int n = wn * 32 + nf * 8 + g;
            uint32_t b0 = Ws[tg * 64 + n];
            uint32_t b1 = Ws[(tg + 4) * 64 + n];
            asm volatile("mma.sync.aligned.m16n8k16.row.col.f32.bf16.bf16.f32 "
                         "{%0,%1,%2,%3}, {%4,%5,%6,%7}, {%8,%9}, {%0,%1,%2,%3};"
                         : "+f"(dacc[nf * 4 + 0]), "+f"(dacc[nf * 4 + 1]),
                           "+f"(dacc[nf * 4 + 2]), "+f"(dacc[nf * 4 + 3])
                         : "r"(a[0]), "r"(a[1]), "r"(a[2]), "r"(a[3]), "r"(b0), "r"(b1));
        }
        __syncthreads();
    }

    // epilogue: thread (g,tg) holds rows g, g+8; cols 2tg, 2tg+1 of each n8
#pragma unroll
    for (int nf = 0; nf < 4; nf++) {
#pragma unroll
        for (int half = 0; half < 2; half++) {
            int m = m0 + wm * 16 + g + half * 8;
#pragma unroll
            for (int t2 = 0; t2 < 2; t2++) {
                int n = n0 + wn * 32 + nf * 8 + tg * 2 + t2;
                if (n < Npad) {
                    float v = dacc[nf * 4 + half * 2 + t2];
                    if (n < Nw) {
                        if (bias) v += bias[n];
                        if (act) v = silu_f(v);
                        if (resid) v += resid[(size_t)m * ldr + n];
                    } else {
                        v = 0.f;
                    }
                    C[(size_t)m * ldc + n] = v;
                }
            }
        }
    }
}

// ---------------------------------------------------------------------------
__global__ __launch_bounds__(256) void copy_feats_kernel(const float* __restrict__ feats) {
    int idx = blockIdx.x * 256 + threadIdx.x;  // over NODES*128
    int n = idx >> 7, c = idx & 127;
    g_XC[(size_t)n * 144 + c] = feats[idx];
}

// ---------------------------------------------------------------------------
// Edge kernel v7: branch-free P1 (LDGs batchable), tensor P2, double-buffered
// SHM. 256 threads, 8 warps, 4 nodes/block, 3 blocks/SM.  (unchanged vs R15)
// ---------------------------------------------------------------------------
#define OFF_WE2P  0                               // u32[272*16]        = 17408
#define OFF_FTA   17408                           // ulonglong2[2*544]  = 17408
#define OFF_W9B   34816                           // float[544]         = 2176
#define OFF_SHM   36992                           // 2 x bf16[32][136]  = 17408
#define SHM_BUF   8704
#define OFF_WC1   54400                           // float[16][64]      = 4096
#define OFF_MS    58496                           // float[32][16]      = 2048
#define OFF_FLT   60544
#define FI_BC1 0
#define FI_WC2 64
#define FI_BE2 128
#define FI_RC  144
#define FI_CW  272
#define FI_EBO 304
#define FI_F2  336                                // ull[32*6] (8B aligned)
#define FI_TOT (336 + 384)
#define EK_SMEM_BYTES (OFF_FLT + FI_TOT*4)        // 63424

#define P1_BODY(SHMb, CBASE, CL) do { \
    int c = (CBASE) + (CL); \
    float av = g_A[aoff + c]; \
    float bv0 = g_B[(size_t)brow0 * EPAD + c]; \
    float bv1 = g_B[(size_t)brow1 * EPAD + c]; \
    float bv2 = g_B[(size_t)brow2 * EPAD + c]; \
    float bv3 = g_B[(size_t)brow3 * EPAD + c]; \
    ulonglong2 w9a0 = FTA[c]; \
    ulonglong2 w9a1 = FTA[EPAD + c]; \
    float w9b = W9Bf[c]; \
    float bvv[4] = {bv0, bv1, bv2, bv3}; \
    _Pragma("unroll") \
    for (int q = 0; q < 4; q++) { \
        ull ha = pack2(fmaf(dd[q], w9b, av + bvv[q]), 0.f); \
        ull hb = 0ull; \
        ffma2(ha, fpa[q][0], w9a0.x); \
        ffma2(hb, fpa[q][1], w9a0.y); \
        ffma2(ha, fpa[q][2], w9a1.x); \
        ffma2(hb, fpa[q][3], w9a1.y); \
        float2 hv = unpack2(fadd2(ha, hb)); \
        (SHMb)[(e0 + q) * 136 + (CL)] = __float2bfloat16(silu_f(hv.x + hv.y)); \
    } } while (0)

__global__ __launch_bounds__(256, 3) void edge_kernel(
    const float* __restrict__ coors,
    const float* __restrict__ We1,
    const float* __restrict__ We2,
    const float* __restrict__ be2,
    const float* __restrict__ Wc1,
    const float* __restrict__ bc1,
    const float* __restrict__ Wc2,
    const float* __restrict__ bc2,
    float* __restrict__ coors_out)
{
    extern __shared__ char smc[];
    uint32_t* We2p = (uint32_t*)(smc + OFF_WE2P);      // [k2][16] bf16x2 pairs
    ulonglong2* FTA = (ulonglong2*)(smc + OFF_FTA);    // [t][c] contiguous
    float* W9Bf = (float*)(smc + OFF_W9B);
    __nv_bfloat16* SHM16 = (__nv_bfloat16*)(smc + OFF_SHM);   // double buffer
    float* SHRf = (float*)(smc + OFF_SHM + SHM_BUF);   // tree overlay on buffer 1
    float* Wc1s = (float*)(smc + OFF_WC1);
    float* msp  = (float*)(smc + OFF_MS);
    float* smf  = (float*)(smc + OFF_FLT);
    float* bc1s = smf + FI_BC1;
    float* Wc2s = smf + FI_WC2;
    float* be2s = smf + FI_BE2;
    float* rc_s = smf + FI_RC;                         // [32][4]
    float* cwp  = smf + FI_CW;                         // [32]
    uint32_t* ebo_s = (uint32_t*)(smf + FI_EBO);       // [32]
    ull* F2u = (ull*)(smf + FI_F2);                    // [32][6]

    int tid = threadIdx.x;
    int w = tid >> 5, lane = tid & 31;
    const unsigned FULL = 0xffffffffu;
    float bc2v = bc2[0];
    uint32_t shm_base0 = smem_u32(smc) + OFF_SHM;

    // ---- weight preamble (once per block) ----
    for (int idx = tid; idx < 272 * 16; idx += 256) {
        int k2 = idx >> 4, n = idx & 15;
        float lo = (2 * k2     < HID) ? We2[(2 * k2)     * 16 + n] : 0.f;
        float hi = (2 * k2 + 1 < HID) ? We2[(2 * k2 + 1) * 16 + n] : 0.f;
        We2p[idx] = bf16x2_pack(lo, hi);
    }
    for (int idx = tid; idx < 2 * EPAD; idx += 256) {
        int t = idx / EPAD, c = idx - t * EPAD;
        ulonglong2 v; v.x = 0ull; v.y = 0ull;
        if (c < HID) {
            v.x = pack2(We1[(size_t)(256 + 4 * t + 0) * HID + c], We1[(size_t)(256 + 4 * t + 1) * HID + c]);
            v.y = pack2(We1[(size_t)(256 + 4 * t + 2) * HID + c], We1[(size_t)(256 + 4 * t + 3) * HID + c]);
        }
        FTA[idx] = v;
    }
    for (int c = tid; c < EPAD; c += 256)
        W9Bf[c] = (c < HID) ? We1[(size_t)264 * HID + c] : 0.f;
    for (int idx = tid; idx < 16 * 64; idx += 256) Wc1s[idx] = Wc1[idx];
    if (tid < 64) { bc1s[tid] = bc1[tid]; Wc2s[tid] = Wc2[tid]; }
    if (tid >= 64 && tid < 80) be2s[tid - 64] = be2[tid - 64];
    __syncthreads();

#pragma unroll 1
    for (int nn = 0; nn < 4; nn++) {
        int node = blockIdx.x * 4 + nn;
        int b = node >> 12, i = node & (NNODES - 1);
        const float* cb = coors + (size_t)b * NNODES * 3;
        size_t aoff = (size_t)node * EPAD;

        // ---- setup (tid<32): knn, rel coords, fourier pairs ----
        if (tid < 32) {
            int e = tid;
            int j = g_knn[(size_t)node * KNN + e];
            ebo_s[e] = (uint32_t)(b * NNODES + j);
            float dx = cb[3 * i + 0] - cb[3 * j + 0];
            float dy = cb[3 * i + 1] - cb[3 * j + 1];
            float dz = cb[3 * i + 2] - cb[3 * j + 2];
            float d = dist2_f(dx, dy, dz);
            rc_s[e * 4 + 0] = dx; rc_s[e * 4 + 1] = dy; rc_s[e * 4 + 2] = dz; rc_s[e * 4 + 3] = 0.f;
            float s0, c0, s1, c1, s2, c2, s3, c3;
            sincosf(d,          &s0, &c0);
            sincosf(d * 0.5f,   &s1, &c1);
            sincosf(d * 0.25f,  &s2, &c2);
            sincosf(d * 0.125f, &s3, &c3);
            F2u[e * 6 + 0] = pack2(s0, s1);
            F2u[e * 6 + 1] = pack2(s2, s3);
            F2u[e * 6 + 2] = pack2(c0, c1);
            F2u[e * 6 + 3] = pack2(c2, c3);
            F2u[e * 6 + 4] = pack2(d, 0.f);
        }
        __syncthreads();

        int e0 = w * 4;
        uint32_t brow0 = ebo_s[e0 + 0], brow1 = ebo_s[e0 + 1];
        uint32_t brow2 = ebo_s[e0 + 2], brow3 = ebo_s[e0 + 3];

        ull fpa[4][4]; float dd[4];
#pragma unroll
        for (int q = 0; q < 4; q++) {
#pragma unroll
            for (int t = 0; t < 4; t++) fpa[q][t] = F2u[(e0 + q) * 6 + t];
            dd[q] = ((const float*)&F2u[(e0 + q) * 6 + 4])[0];
        }

        float dacc[16];
#pragma unroll
        for (int p = 0; p < 16; p++) dacc[p] = 0.f;

        // ---- main chunks 0..3: branch-free P1 (batched LDGs) + full P2 ----
#pragma unroll 1
        for (int chunk = 0; chunk < 4; chunk++) {
            int cbase = chunk * 128;
            int buf = chunk & 1;
            __nv_bfloat16* SHMb = SHM16 + buf * (SHM_BUF / 2);

#pragma unroll
            for (int it = 0; it < 4; it++) {
                int cl = it * 32 + lane;
                P1_BODY(SHMb, cbase, cl);
            }
            __syncthreads();

            {
                int k2b = chunk * 64 + w * 8;
                int bufb = buf * SHM_BUF;
                int row = lane & 15, kh = (lane >> 4) * 8;
                uint32_t addr0 = shm_base0 + (uint32_t)bufb
                               + (uint32_t)(row * 272 + (w * 16 + kh) * 2);
                uint32_t addr1 = addr0 + 16u * 272u;
                uint32_t a0[4], a1[4];
                asm volatile("ldmatrix.sync.aligned.m8n8.x4.shared.b16 {%0,%1,%2,%3}, [%4];"
                             : "=r"(a0[0]), "=r"(a0[1]), "=r"(a0[2]), "=r"(a0[3]) : "r"(addr0));
                asm volatile("ldmatrix.sync.aligned.m8n8.x4.shared.b16 {%0,%1,%2,%3}, [%4];"
                             : "=r"(a1[0]), "=r"(a1[1]), "=r"(a1[2]), "=r"(a1[3]) : "r"(addr1));
                int g = lane >> 2, tg = lane & 3;
                uint32_t b00 = We2p[(k2b + tg) * 16 + g];
                uint32_t b01 = We2p[(k2b + tg + 4) * 16 + g];
                uint32_t b10 = We2p[(k2b + tg) * 16 + 8 + g];
                uint32_t b11 = We2p[(k2b + tg + 4) * 16 + 8 + g];
                asm volatile("mma.sync.aligned.m16n8k16.row.col.f32.bf16.bf16.f32 "
                             "{%0,%1,%2,%3}, {%4,%5,%6,%7}, {%8,%9}, {%0,%1,%2,%3};"
                             : "+f"(dacc[0]), "+f"(dacc[1]), "+f"(dacc[2]), "+f"(dacc[3])
                             : "r"(a0[0]), "r"(a0[1]), "r"(a0[2]), "r"(a0[3]), "r"(b00), "r"(b01));
                asm volatile("mma.sync.aligned.m16n8k16.row.col.f32.bf16.bf16.f32 "
                             "{%0,%1,%2,%3}, {%4,%5,%6,%7}, {%8,%9}, {%0,%1,%2,%3};"
                             : "+f"(dacc[4]), "+f"(dacc[5]), "+f"(dacc[6]), "+f"(dacc[7])
                             : "r"(a0[0]), "r"(a0[1]), "r"(a0[2]), "r"(a0[3]), "r"(b10), "r"(b11));
                asm volatile("mma.sync.aligned.m16n8k16.row.col.f32.bf16.bf16.f32 "
                             "{%0,%1,%2,%3}, {%4,%5,%6,%7}, {%8,%9}, {%0,%1,%2,%3};"
                             : "+f"(dacc[8]), "+f"(dacc[9]), "+f"(dacc[10]), "+f"(dacc[11])
                             : "r"(a1[0]), "r"(a1[1]), "r"(a1[2]), "r"(a1[3]), "r"(b00), "r"(b01));
                asm volatile("mma.sync.aligned.m16n8k16.row.col.f32.bf16.bf16.f32 "
                             "{%0,%1,%2,%3}, {%4,%5,%6,%7}, {%8,%9}, {%0,%1,%2,%3};"
                             : "+f"(dacc[12]), "+f"(dacc[13]), "+f"(dacc[14]), "+f"(dacc[15])
                             : "r"(a1[0]), "r"(a1[1]), "r"(a1[2]), "r"(a1[3]), "r"(b10), "r"(b11));
            }
            // no trailing sync: next P1 writes the OTHER buffer.
        }

        // ---- tail chunk (channels 512..543), buffer 0 ----
        {
            P1_BODY(SHM16, 512, lane);
        }
        __syncthreads();
        if (w < 2) {
            int k2b = 256 + w * 8;
            int row = lane & 15, kh = (lane >> 4) * 8;
            uint32_t addr0 = shm_base0 + (uint32_t)(row * 272 + (w * 16 + kh) * 2);
            uint32_t addr1 = addr0 + 16u * 272u;
            uint32_t a0[4], a1[4];
            asm volatile("ldmatrix.sync.aligned.m8n8.x4.shared.b16 {%0,%1,%2,%3}, [%4];"
                         : "=r"(a0[0]), "=r"(a0[1]), "=r"(a0[2]), "=r"(a0[3]) : "r"(addr0));
            asm volatile("ldmatrix.sync.aligned.m8n8.x4.shared.b16 {%0,%1,%2,%3}, [%4];"
                         : "=r"(a1[0]), "=r"(a1[1]), "=r"(a1[2]), "=r"(a1[3]) : "r"(addr1));
            int g = lane >> 2, tg = lane & 3;
            uint32_t b00 = We2p[(k2b + tg) * 16 + g];
            uint32_t b01 = We2p[(k2b + tg + 4) * 16 + g];
            uint32_t b10 = We2p[(k2b + tg) * 16 + 8 + g];
            uint32_t b11 = We2p[(k2b + tg + 4) * 16 + 8 + g];
            asm volatile("mma.sync.aligned.m16n8k16.row.col.f32.bf16.bf16.f32 "
                         "{%0,%1,%2,%3}, {%4,%5,%6,%7}, {%8,%9}, {%0,%1,%2,%3};"
                         : "+f"(dacc[0]), "+f"(dacc[1]), "+f"(dacc[2]), "+f"(dacc[3])
                         : "r"(a0[0]), "r"(a0[1]), "r"(a0[2]), "r"(a0[3]), "r"(b00), "r"(b01));
            asm volatile("mma.sync.aligned.m16n8k16.row.col.f32.bf16.bf16.f32 "
                         "{%0,%1,%2,%3}, {%4,%5,%6,%7}, {%8,%9}, {%0,%1,%2,%3};"
                         : "+f"(dacc[4]), "+f"(dacc[5]), "+f"(dacc[6]), "+f"(dacc[7])
                         : "r"(a0[0]), "r"(a0[1]), "r"(a0[2]), "r"(a0[3]), "r"(b10), "r"(b11));
            asm volatile("mma.sync.aligned.m16n8k16.row.col.f32.bf16.bf16.f32 "
                         "{%0,%1,%2,%3}, {%4,%5,%6,%7}, {%8,%9}, {%0,%1,%2,%3};"
                         : "+f"(dacc[8]), "+f"(dacc[9]), "+f"(dacc[10]), "+f"(dacc[11])
                         : "r"(a1[0]), "r"(a1[1]), "r"(a1[2]), "r"(a1[3]), "r"(b00), "r"(b01));
            asm volatile("mma.sync.aligned.m16n8k16.row.col.f32.bf16.bf16.f32 "
                         "{%0,%1,%2,%3}, {%4,%5,%6,%7}, {%8,%9}, {%0,%1,%2,%3};"
                         : "+f"(dacc[12]), "+f"(dacc[13]), "+f"(dacc[14]), "+f"(dacc[15])
                         : "r"(a1[0]), "r"(a1[1]), "r"(a1[2]), "r"(a1[3]), "r"(b10), "r"(b11));
        }

        // ---- tree reduction of dacc across 8 warps (overlay on buffer 1) ----
#pragma unroll 1
        for (int step = 0; step < 3; step++) {
            int half = 4 >> step;              // 4, 2, 1
            if (w >= half && w < 2 * half) {
#pragma unroll
                for (int r4 = 0; r4 < 4; r4++)
                    *(float4*)(SHRf + (w - half) * 512 + lane * 16 + r4 * 4) =
                        make_float4(dacc[r4 * 4 + 0], dacc[r4 * 4 + 1],
                                    dacc[r4 * 4 + 2], dacc[r4 * 4 + 3]);
            }
            __syncthreads();
            if (w < half) {
#pragma unroll
                for (int r4 = 0; r4 < 4; r4++) {
                    float4 v = *(const float4*)(SHRf + w * 512 + lane * 16 + r4 * 4);
                    dacc[r4 * 4 + 0] += v.x; dacc[r4 * 4 + 1] += v.y;
                    dacc[r4 * 4 + 2] += v.z; dacc[r4 * 4 + 3] += v.w;
                }
            }
            __syncthreads();
        }
        if (w == 0) {
            int g = lane >> 2, tg = lane & 3;
#pragma unroll
            for (int mt = 0; mt < 2; mt++)
#pragma unroll
                for (int nt = 0; nt < 2; nt++) {
                    int e = mt * 16 + g, k = nt * 8 + tg * 2;
                    const float* dp = &dacc[mt * 8 + nt * 4];
                    msp[e * 16 + k + 0]       = silu_f(dp[0] + be2s[k + 0]);
                    msp[e * 16 + k + 1]       = silu_f(dp[1] + be2s[k + 1]);
                    msp[(e + 8) * 16 + k + 0] = silu_f(dp[2] + be2s[k + 0]);
                    msp[(e + 8) * 16 + k + 1] = silu_f(dp[3] + be2s[k + 1]);
                }
        }
        __syncthreads();

        // ---- coors MLP: 8 threads per edge (ms hoisted to registers) ----
        {
            int e = tid >> 3, li = tid & 7;
            float mloc[16];
#pragma unroll
            for (int r4 = 0; r4 < 4; r4++) {
                float4 v = *(const float4*)(msp + e * 16 + r4 * 4);
                mloc[r4 * 4 + 0] = v.x; mloc[r4 * 4 + 1] = v.y;
                mloc[r4 * 4 + 2] = v.z; mloc[r4 * 4 + 3] = v.w;
            }
            float wpart = 0.f;
#pragma unroll
            for (int q = 0; q < 8; q++) {
                int l = li * 8 + q;
                float u = bc1s[l];
#pragma unroll
                for (int k = 0; k < 16; k++)
                    u = fmaf(mloc[k], Wc1s[k * 64 + l], u);
                wpart = fmaf(silu_f(u), Wc2s[l], wpart);
            }
            wpart += __shfl_xor_sync(FULL, wpart, 1);
            wpart += __shfl_xor_sync(FULL, wpart, 2);
            wpart += __shfl_xor_sync(FULL, wpart, 4);
            if (li == 0) cwp[e] = wpart + bc2v;
        }
        __syncthreads();

        // ---- m_i (threads 0-15) and coors_out (warp 1) ----
        if (tid < 16) {
            float s = 0.f;
#pragma unroll 8
            for (int e2 = 0; e2 < 32; e2++) s += msp[e2 * 16 + tid];
            g_XC[(size_t)node * 144 + 128 + tid] = s;
        }
        if (w == 1) {
            int e2 = lane;
            float wv = cwp[e2];
            float px = wv * rc_s[e2 * 4 + 0];
            float py = wv * rc_s[e2 * 4 + 1];
            float pz = wv * rc_s[e2 * 4 + 2];
#pragma unroll
            for (int off = 16; off > 0; off >>= 1) {
                px += __shfl_down_sync(FULL, px, off);
                py += __shfl_down_sync(FULL, py, off);
                pz += __shfl_down_sync(FULL, pz, off);
            }
            if (e2 == 0) {
                float* co = coors_out + (size_t)node * 3;
                co[0] = cb[3 * i + 0] + px;
                co[1] = cb[3 * i + 1] + py;
                co[2] = cb[3 * i + 2] + pz;
            }
        }
        __syncthreads();
    }
}

// ---------------------------------------------------------------------------
extern "C" void kernel_launch(void* const* d_in, const int* in_sizes, int n_in,
                              void* d_out, int out_size) {
    const float* feats = (const float*)d_in[0];
    const float* coors = (const float*)d_in[1];
    const float* We1   = (const float*)d_in[2];
    const float* be1   = (const float*)d_in[3];
    const float* We2   = (const float*)d_in[4];
    const float* be2   = (const float*)d_in[5];
    const float* Wc1   = (const float*)d_in[6];
    const float* bc1   = (const float*)d_in[7];
    const float* Wc2   = (const float*)d_in[8];
    const float* bc2   = (const float*)d_in[9];
    const float* Wn1   = (const float*)d_in[10];
    const float* bn1   = (const float*)d_in[11];
    const float* Wn2   = (const float*)d_in[12];
    const float* bn2   = (const float*)d_in[13];
    float* out = (float*)d_out;
    float* node_out  = out;
    float* coors_out = out + NODE_OUT_ELEMS;

    float *pA, *pB, *pXC, *pH1;
    cudaGetSymbolAddress((void**)&pA, g_A);
    cudaGetSymbolAddress((void**)&pB, g_B);
    cudaGetSymbolAddress((void**)&pXC, g_XC);
    cudaGetSymbolAddress((void**)&pH1, g_H1);

    cudaFuncSetAttribute(edge_kernel, cudaFuncAttributeMaxDynamicSharedMemorySize, EK_SMEM_BYTES);

    // 1) KNN
    knn_kernel<<<NODES / 8, 256>>>(coors);

    // 2) A = feats @ We1[0:128,:] + be1 ; B = feats @ We1[128:256,:]  (pad->544)
    gemm16_kernel<<<dim3(9, NODES / 64), 256>>>(feats, DIMF, We1, HID, be1, nullptr, 0,
                                                pA, EPAD, HID, EPAD, DIMF, 0);
    gemm16_kernel<<<dim3(9, NODES / 64), 256>>>(feats, DIMF, We1 + 128 * HID, HID, nullptr, nullptr, 0,
                                                pB, EPAD, HID, EPAD, DIMF, 0);

    // 3) edges: m_ij -> m_i (XC[:,128:144]), coors_out
    edge_kernel<<<NODES / 4, 256, EK_SMEM_BYTES>>>(coors, We1, We2, be2,
                                                   Wc1, bc1, Wc2, bc2, coors_out);

    // 4) XC[:, 0:128] = feats
    copy_feats_kernel<<<(NODES * DIMF) / 256, 256>>>(feats);

    // 5) node MLP (tensor path)
    gemm16_kernel<<<dim3(4, NODES / 64), 256>>>(pXC, 144, Wn1, 256, bn1, nullptr, 0,
                                                pH1, 256, 256, 256, 144, 1);
    gemm16_kernel<<<dim3(2, NODES / 64), 256>>>(pH1, 256, Wn2, DIMF, bn2, feats, DIMF,
                                                node_out, DIMF, DIMF, DIMF, 256, 0);
}